// round 5
// baseline (speedup 1.0000x reference)
#include <cuda_runtime.h>
#include <cuda_bf16.h>
#include <math.h>
#include <stdint.h>

// ---------------- problem constants ----------------
#define BB 4
#define SS 1024
#define DD 1024
#define HH 16
#define DHH 64
#define FFN 4096
#define ROWS (BB*SS)   // 4096

// ---------------- device scratch ----------------
__device__ float g_o1 [ROWS*DD];
__device__ __nv_bfloat16 g_xh[ROWS*DD];
__device__ __nv_bfloat16 g_xl[ROWS*DD];
__device__ __nv_bfloat16 g_mh[(size_t)ROWS*FFN];
__device__ __nv_bfloat16 g_ml[(size_t)ROWS*FFN];
__device__ __nv_bfloat16 g_qh[ROWS*DD];
__device__ __nv_bfloat16 g_ql[ROWS*DD];
__device__ __nv_bfloat16 g_kh[ROWS*DD];
__device__ __nv_bfloat16 g_kl[ROWS*DD];
__device__ __nv_bfloat16 g_vh[ROWS*DD];
__device__ __nv_bfloat16 g_vl[ROWS*DD];
__device__ __nv_bfloat16 g_wqt[2][DD*DD];
__device__ __nv_bfloat16 g_wkt[2][DD*DD];
__device__ __nv_bfloat16 g_wvt[2][DD*DD];
__device__ __nv_bfloat16 g_wot[2][DD*DD];
__device__ __nv_bfloat16 g_w1t[2][(size_t)DD*FFN];
__device__ __nv_bfloat16 g_w2t[2][(size_t)DD*FFN];

// ---------------- small helpers ----------------
__device__ __forceinline__ uint32_t smem_u32(const void* p) {
    uint32_t a;
    asm("{ .reg .u64 t; cvta.to.shared.u64 t, %1; cvt.u32.u64 %0, t; }" : "=r"(a) : "l"(p));
    return a;
}
__device__ __forceinline__ void cp_async16(uint32_t s, const void* g) {
    asm volatile("cp.async.cg.shared.global [%0], [%1], 16;" :: "r"(s), "l"(g));
}
__device__ __forceinline__ void ldsm_x4(uint32_t* r, uint32_t addr) {
    asm volatile("ldmatrix.sync.aligned.m8n8.x4.shared.b16 {%0,%1,%2,%3}, [%4];"
        : "=r"(r[0]), "=r"(r[1]), "=r"(r[2]), "=r"(r[3]) : "r"(addr));
}
__device__ __forceinline__ void ldsm_x4_t(uint32_t* r, uint32_t addr) {
    asm volatile("ldmatrix.sync.aligned.m8n8.x4.trans.shared.b16 {%0,%1,%2,%3}, [%4];"
        : "=r"(r[0]), "=r"(r[1]), "=r"(r[2]), "=r"(r[3]) : "r"(addr));
}
__device__ __forceinline__ void mma16816(float* d, const uint32_t* a, const uint32_t* b) {
    asm volatile("mma.sync.aligned.m16n8k16.row.col.f32.bf16.bf16.f32 "
        "{%0,%1,%2,%3}, {%4,%5,%6,%7}, {%8,%9}, {%0,%1,%2,%3};"
        : "+f"(d[0]), "+f"(d[1]), "+f"(d[2]), "+f"(d[3])
        : "r"(a[0]), "r"(a[1]), "r"(a[2]), "r"(a[3]), "r"(b[0]), "r"(b[1]));
}
__device__ __forceinline__ void split_bf16(float v, __nv_bfloat16& h, __nv_bfloat16& l) {
    h = __float2bfloat16_rn(v);
    l = __float2bfloat16_rn(v - __bfloat162float(h));
}
__device__ __forceinline__ uint32_t pack_bf(__nv_bfloat16 a, __nv_bfloat16 b) {
    return (uint32_t)__bfloat16_as_ushort(a) | ((uint32_t)__bfloat16_as_ushort(b) << 16);
}

// ---------------- weight convert + transpose ----------------
__global__ void wconv(const float* __restrict__ W, __nv_bfloat16* __restrict__ Th,
                      __nv_bfloat16* __restrict__ Tl, int K, int N)
{
    __shared__ float tile[32][33];
    int tx = threadIdx.x, ty = threadIdx.y;      // 32 x 8
    int n0 = blockIdx.x * 32, k0 = blockIdx.y * 32;
    #pragma unroll
    for (int i = 0; i < 4; i++)
        tile[ty + i*8][tx] = W[(size_t)(k0 + ty + i*8) * N + n0 + tx];
    __syncthreads();
    #pragma unroll
    for (int i = 0; i < 4; i++) {
        int n = n0 + ty + i*8;
        int k = k0 + tx;
        float v = tile[tx][ty + i*8];
        __nv_bfloat16 h, l; split_bf16(v, h, l);
        Th[(size_t)n * K + k] = h;
        Tl[(size_t)n * K + k] = l;
    }
}

// ---------------- LayerNorm -> bf16 hi/lo ----------------
__global__ void layernorm_bf(const float* __restrict__ x, const float* __restrict__ g,
                             const float* __restrict__ b,
                             __nv_bfloat16* __restrict__ oh, __nv_bfloat16* __restrict__ ol)
{
    __shared__ float red0[8], red1[8];
    int row = blockIdx.x, tid = threadIdx.x;
    const float4* xr = (const float4*)(x + (size_t)row * DD);
    float4 v = xr[tid];
    float s  = v.x + v.y + v.z + v.w;
    float s2 = v.x*v.x + v.y*v.y + v.z*v.z + v.w*v.w;
    #pragma unroll
    for (int o = 16; o; o >>= 1) {
        s  += __shfl_xor_sync(0xffffffffu, s,  o);
        s2 += __shfl_xor_sync(0xffffffffu, s2, o);
    }
    if ((tid & 31) == 0) { red0[tid >> 5] = s; red1[tid >> 5] = s2; }
    __syncthreads();
    float S = 0.f, S2 = 0.f;
    #pragma unroll
    for (int i = 0; i < 8; i++) { S += red0[i]; S2 += red1[i]; }
    float mean = S * (1.f / DD);
    float var  = S2 * (1.f / DD) - mean * mean;
    float rstd = rsqrtf(var + 1e-5f);
    float4 gv = ((const float4*)g)[tid];
    float4 bv = ((const float4*)b)[tid];
    float o[4];
    o[0] = (v.x - mean) * rstd * gv.x + bv.x;
    o[1] = (v.y - mean) * rstd * gv.y + bv.y;
    o[2] = (v.z - mean) * rstd * gv.z + bv.z;
    o[3] = (v.w - mean) * rstd * gv.w + bv.w;
    __nv_bfloat16 h[4], l[4];
    #pragma unroll
    for (int i = 0; i < 4; i++) split_bf16(o[i], h[i], l[i]);
    size_t base = (size_t)row * DD + tid * 4;
    *(__nv_bfloat162*)(oh + base)     = __nv_bfloat162(h[0], h[1]);
    *(__nv_bfloat162*)(oh + base + 2) = __nv_bfloat162(h[2], h[3]);
    *(__nv_bfloat162*)(ol + base)     = __nv_bfloat162(l[0], l[1]);
    *(__nv_bfloat162*)(ol + base + 2) = __nv_bfloat162(l[2], l[3]);
}

// ---------------- tensor-core GEMM via mma.sync ----------------
// CTA tile 256(M) x 128(N), 8 warps (4 Mgroups x 2 Ngroups), warp tile 64x64.
// BK=32, double-buffered cp.async.
// smem per stage: Ah(20480) Al(20480) Bh(10240) Bl(10240) = 61440
// EPI 2: bias + residual -> fp32 C
// EPI 3: bias + GELU -> bf16 hi/lo (Ch/Cl)
// EPI 4: (bias + val) * scl -> bf16 hi/lo scattered to (B,H,S,DH)
#define LDB 80
#define A_SZ 20480
#define B_SZ 10240
#define STG_SZ 61440
template<int EPI>
__global__ void __launch_bounds__(256)
gemm_mma(const __nv_bfloat16* __restrict__ Ah, const __nv_bfloat16* __restrict__ Al,
         const __nv_bfloat16* __restrict__ Wh, const __nv_bfloat16* __restrict__ Wl,
         const float* __restrict__ bias, const float* __restrict__ res,
         float* __restrict__ C, __nv_bfloat16* __restrict__ Ch, __nv_bfloat16* __restrict__ Cl,
         int M, int N, int K, float scl)
{
    extern __shared__ char smem[];
    const uint32_t sb = smem_u32(smem);
    const int tid = threadIdx.x;
    const int wid = tid >> 5, lane = tid & 31;
    const int wm = wid & 3, wn = wid >> 2;
    const int m0 = blockIdx.y * 256, n0 = blockIdx.x * 128;

    float acc[4][8][4] = {};
    const int NK = K >> 5;

    auto load_stage = [&](int kc, int buf) {
        int k0 = kc << 5;
        uint32_t stb = sb + buf * STG_SZ;
        #pragma unroll
        for (int i = 0; i < 12; i++) {
            int c = tid + i * 256;     // 0..3071
            if (c < 2048) {            // A: hi [0,1024), lo [1024,2048)
                int arr = c >> 10;
                int cc = c & 1023;
                int row = cc >> 2, col = cc & 3;
                const __nv_bfloat16* gsrc = (arr ? Al : Ah) + (size_t)(m0 + row) * K + k0 + col * 8;
                cp_async16(stb + arr * A_SZ + row * LDB + col * 16, gsrc);
            } else {                   // B: hi [2048,2560), lo [2560,3072)
                int c2 = c - 2048;
                int arr = c2 >> 9;
                int cc = c2 & 511;
                int row = cc >> 2, col = cc & 3;
                const __nv_bfloat16* gsrc = (arr ? Wl : Wh) + (size_t)(n0 + row) * K + k0 + col * 8;
                cp_async16(stb + 2 * A_SZ + arr * B_SZ + row * LDB + col * 16, gsrc);
            }
        }
        asm volatile("cp.async.commit_group;" ::: "memory");
    };

    load_stage(0, 0);

    for (int kc = 0; kc < NK; kc++) {
        int buf = kc & 1;
        if (kc + 1 < NK) {
            load_stage(kc + 1, buf ^ 1);
            asm volatile("cp.async.wait_group 1;" ::: "memory");
        } else {
            asm volatile("cp.async.wait_group 0;" ::: "memory");
        }
        __syncthreads();

        uint32_t stb = sb + buf * STG_SZ;
        #pragma unroll
        for (int ks = 0; ks < 2; ks++) {
            uint32_t Af[4][4], Af2[4][4], Bf[8][2];
            int ar = lane & 15, ac = ks * 16 + (lane >> 4) * 8;
            #pragma unroll
            for (int mt = 0; mt < 4; mt++) {
                uint32_t a = stb + (wm * 64 + mt * 16 + ar) * LDB + ac * 2;
                ldsm_x4(Af[mt], a);
                ldsm_x4(Af2[mt], a + A_SZ);
            }
            int gq = lane >> 3, l8 = lane & 7;
            int br = (gq >> 1) * 8 + l8, bc = ks * 16 + (gq & 1) * 8;
            // --- B hi ---
            #pragma unroll
            for (int p = 0; p < 4; p++) {
                uint32_t a = stb + 2 * A_SZ + (wn * 64 + p * 16 + br) * LDB + bc * 2;
                uint32_t t[4];
                ldsm_x4(t, a);
                Bf[2*p][0] = t[0]; Bf[2*p][1] = t[1];
                Bf[2*p+1][0] = t[2]; Bf[2*p+1][1] = t[3];
            }
            #pragma unroll
            for (int mt = 0; mt < 4; mt++)
                #pragma unroll
                for (int nt = 0; nt < 8; nt++) {
                    mma16816(acc[mt][nt], Af[mt],  Bf[nt]);
                    mma16816(acc[mt][nt], Af2[mt], Bf[nt]);
                }
            // --- B lo (reuse Bf regs) ---
            #pragma unroll
            for (int p = 0; p < 4; p++) {
                uint32_t a = stb + 2 * A_SZ + B_SZ + (wn * 64 + p * 16 + br) * LDB + bc * 2;
                uint32_t t[4];
                ldsm_x4(t, a);
                Bf[2*p][0] = t[0]; Bf[2*p][1] = t[1];
                Bf[2*p+1][0] = t[2]; Bf[2*p+1][1] = t[3];
            }
            #pragma unroll
            for (int mt = 0; mt < 4; mt++)
                #pragma unroll
                for (int nt = 0; nt < 8; nt++)
                    mma16816(acc[mt][nt], Af[mt], Bf[nt]);
        }
        __syncthreads();
    }

    // ---- epilogue ----
    int rb = m0 + wm * 64 + (lane >> 2);
    int cb = n0 + wn * 64 + (lane & 3) * 2;
    #pragma unroll
    for (int mt = 0; mt < 4; mt++) {
        #pragma unroll
        for (int half = 0; half < 2; half++) {
            int r = rb + mt * 16 + half * 8;
            #pragma unroll
            for (int nt = 0; nt < 8; nt++) {
                int n = cb + nt * 8;
                float2 bv = *(const float2*)(bias + n);
                float v0 = acc[mt][nt][half * 2 + 0] + bv.x;
                float v1 = acc[mt][nt][half * 2 + 1] + bv.y;
                if (EPI == 2) {
                    float2 rv = *(const float2*)(res + (size_t)r * N + n);
                    v0 += rv.x; v1 += rv.y;
                    *(float2*)(C + (size_t)r * N + n) = make_float2(v0, v1);
                } else if (EPI == 3) {
                    v0 = 0.5f * v0 * (1.0f + erff(v0 * 0.70710678118654752f));
                    v1 = 0.5f * v1 * (1.0f + erff(v1 * 0.70710678118654752f));
                    __nv_bfloat16 h0, l0, h1, l1;
                    split_bf16(v0, h0, l0); split_bf16(v1, h1, l1);
                    *(__nv_bfloat162*)(Ch + (size_t)r * N + n) = __nv_bfloat162(h0, h1);
                    *(__nv_bfloat162*)(Cl + (size_t)r * N + n) = __nv_bfloat162(l0, l1);
                } else if (EPI == 4) {
                    v0 *= scl; v1 *= scl;
                    __nv_bfloat16 h0, l0, h1, l1;
                    split_bf16(v0, h0, l0); split_bf16(v1, h1, l1);
                    int b_ = r >> 10, s = r & 1023, hh = n >> 6, dh = n & 63;
                    size_t off = ((size_t)(b_ * HH + hh) * SS + s) * DHH + dh;
                    *(__nv_bfloat162*)(Ch + off) = __nv_bfloat162(h0, h1);
                    *(__nv_bfloat162*)(Cl + off) = __nv_bfloat162(l0, l1);
                }
            }
        }
    }
}

// ---------------- Flash attention via mma.sync ----------------
#define LDK 144
#define FQ_SZ 18432
#define FST0  36864
#define FST_SZ 36864
#define FARR  9216
#define FLASH_SMEM (FST0 + 2*FST_SZ)   // 110592
__global__ void __launch_bounds__(256)
flash_mma(const __nv_bfloat16* __restrict__ Qh_, const __nv_bfloat16* __restrict__ Ql_,
          const __nv_bfloat16* __restrict__ Kh_, const __nv_bfloat16* __restrict__ Kl_,
          const __nv_bfloat16* __restrict__ Vh_, const __nv_bfloat16* __restrict__ Vl_,
          __nv_bfloat16* __restrict__ Oh, __nv_bfloat16* __restrict__ Ol)
{
    extern __shared__ char smc[];
    const uint32_t sb = smem_u32(smc);
    int tid = threadIdx.x, lane = tid & 31, w = tid >> 5;
    int bh = blockIdx.y, q0 = blockIdx.x * 128;
    size_t qbase = ((size_t)bh * SS + q0) * DHH;
    size_t kvbase = (size_t)bh * SS * DHH;

    #pragma unroll
    for (int i = 0; i < 8; i++) {
        int c = tid + i * 256;
        int arr = c >> 10, cc = c & 1023;
        int row = cc >> 3, col = cc & 7;
        const __nv_bfloat16* src = (arr ? Ql_ : Qh_) + qbase + row * 64 + col * 8;
        cp_async16(sb + arr * FQ_SZ + row * LDK + col * 16, src);
    }
    auto load_stage = [&](int t, int buf) {
        size_t base = kvbase + (size_t)t * 64 * DHH;
        #pragma unroll
        for (int i = 0; i < 8; i++) {
            int c = tid + i * 256;
            int arr = c >> 9, cc = c & 511;
            int row = cc >> 3, col = cc & 7;
            const __nv_bfloat16* src;
            if      (arr == 0) src = Kh_;
            else if (arr == 1) src = Kl_;
            else if (arr == 2) src = Vh_;
            else               src = Vl_;
            src += base + row * 64 + col * 8;
            cp_async16(sb + FST0 + buf * FST_SZ + arr * FARR + row * LDK + col * 16, src);
        }
    };
    load_stage(0, 0);
    asm volatile("cp.async.commit_group;" ::: "memory");

    uint32_t qh[4][4], ql[4][4];
    float m2[2] = {-1e30f, -1e30f}, l2[2] = {0.f, 0.f};
    float acc_o[8][4] = {};

    for (int t = 0; t < SS / 64; t++) {
        int buf = t & 1;
        if (t + 1 < SS / 64) {
            load_stage(t + 1, (t + 1) & 1);
            asm volatile("cp.async.commit_group;" ::: "memory");
            asm volatile("cp.async.wait_group 1;" ::: "memory");
        } else {
            asm volatile("cp.async.wait_group 0;" ::: "memory");
        }
        __syncthreads();
        if (t == 0) {
            #pragma unroll
            for (int ks = 0; ks < 4; ks++) {
                uint32_t a = sb + (w * 16 + (lane & 15)) * LDK + ks * 32 + (lane >> 4) * 16;
                ldsm_x4(qh[ks], a);
                ldsm_x4(ql[ks], a + FQ_SZ);
            }
        }
        uint32_t stb = sb + FST0 + buf * FST_SZ;

        float s[8][4] = {};
        int gq = lane >> 3, l8 = lane & 7;
        int br = (gq >> 1) * 8 + l8;
        #pragma unroll
        for (int ks = 0; ks < 4; ks++) {
            uint32_t Bh[8][2], Bl[8][2];
            int bcB = ks * 32 + (gq & 1) * 16;
            #pragma unroll
            for (int p = 0; p < 4; p++) {
                uint32_t a = stb + (p * 16 + br) * LDK + bcB;
                uint32_t t4[4];
                ldsm_x4(t4, a);
                Bh[2*p][0] = t4[0]; Bh[2*p][1] = t4[1];
                Bh[2*p+1][0] = t4[2]; Bh[2*p+1][1] = t4[3];
                ldsm_x4(t4, a + FARR);
                Bl[2*p][0] = t4[0]; Bl[2*p][1] = t4[1];
                Bl[2*p+1][0] = t4[2]; Bl[2*p+1][1] = t4[3];
            }
            #pragma unroll
            for (int nt = 0; nt < 8; nt++) {
                mma16816(s[nt], qh[ks], Bh[nt]);
                mma16816(s[nt], qh[ks], Bl[nt]);
                mma16816(s[nt], ql[ks], Bh[nt]);
            }
        }

        float rm0 = -1e30f, rm1 = -1e30f;
        #pragma unroll
        for (int nt = 0; nt < 8; nt++) {
            rm0 = fmaxf(rm0, fmaxf(s[nt][0], s[nt][1]));
            rm1 = fmaxf(rm1, fmaxf(s[nt][2], s[nt][3]));
        }
        rm0 = fmaxf(rm0, __shfl_xor_sync(0xffffffffu, rm0, 1));
        rm0 = fmaxf(rm0, __shfl_xor_sync(0xffffffffu, rm0, 2));
        rm1 = fmaxf(rm1, __shfl_xor_sync(0xffffffffu, rm1, 1));
        rm1 = fmaxf(rm1, __shfl_xor_sync(0xffffffffu, rm1, 2));
        float mn0 = fmaxf(m2[0], rm0), mn1 = fmaxf(m2[1], rm1);
        float al0 = __expf(m2[0] - mn0), al1 = __expf(m2[1] - mn1);
        float rs0 = 0.f, rs1 = 0.f;
        #pragma unroll
        for (int nt = 0; nt < 8; nt++) {
            s[nt][0] = __expf(s[nt][0] - mn0);
            s[nt][1] = __expf(s[nt][1] - mn0);
            s[nt][2] = __expf(s[nt][2] - mn1);
            s[nt][3] = __expf(s[nt][3] - mn1);
            rs0 += s[nt][0] + s[nt][1];
            rs1 += s[nt][2] + s[nt][3];
        }
        rs0 += __shfl_xor_sync(0xffffffffu, rs0, 1);
        rs0 += __shfl_xor_sync(0xffffffffu, rs0, 2);
        rs1 += __shfl_xor_sync(0xffffffffu, rs1, 1);
        rs1 += __shfl_xor_sync(0xffffffffu, rs1, 2);
        l2[0] = l2[0] * al0 + rs0;
        l2[1] = l2[1] * al1 + rs1;
        m2[0] = mn0; m2[1] = mn1;
        #pragma unroll
        for (int nt = 0; nt < 8; nt++) {
            acc_o[nt][0] *= al0; acc_o[nt][1] *= al0;
            acc_o[nt][2] *= al1; acc_o[nt][3] *= al1;
        }

        int vr = ((lane >> 3) & 1) * 8 + (lane & 7);
        int vcb = ((lane >> 4) * 8) * 2;
        #pragma unroll
        for (int ks = 0; ks < 4; ks++) {
            uint32_t ph[4], pl[4];
            #pragma unroll
            for (int q2 = 0; q2 < 2; q2++) {
                float p0 = s[2*ks + q2][0], p1 = s[2*ks + q2][1];
                float p2 = s[2*ks + q2][2], p3 = s[2*ks + q2][3];
                __nv_bfloat16 h0,lo0,h1,lo1,h2,lo2,h3,lo3;
                split_bf16(p0, h0, lo0); split_bf16(p1, h1, lo1);
                split_bf16(p2, h2, lo2); split_bf16(p3, h3, lo3);
                ph[2*q2]     = pack_bf(h0, h1);  pl[2*q2]     = pack_bf(lo0, lo1);
                ph[2*q2 + 1] = pack_bf(h2, h3);  pl[2*q2 + 1] = pack_bf(lo2, lo3);
            }
            uint32_t Vh[8][2], Vl[8][2];
            #pragma unroll
            for (int np = 0; np < 4; np++) {
                uint32_t a = stb + 2 * FARR + (ks * 16 + vr) * LDK + np * 32 + vcb;
                uint32_t t4[4];
                ldsm_x4_t(t4, a);
                Vh[2*np][0] = t4[0]; Vh[2*np][1] = t4[1];
                Vh[2*np+1][0] = t4[2]; Vh[2*np+1][1] = t4[3];
                ldsm_x4_t(t4, a + FARR);
                Vl[2*np][0] = t4[0]; Vl[2*np][1] = t4[1];
                Vl[2*np+1][0] = t4[2]; Vl[2*np+1][1] = t4[3];
            }
            #pragma unroll
            for (int nt = 0; nt < 8; nt++) {
                mma16816(acc_o[nt], ph, Vh[nt]);
                mma16816(acc_o[nt], ph, Vl[nt]);
                mma16816(acc_o[nt], pl, Vh[nt]);
            }
        }
        __syncthreads();
    }

    float inv0 = 1.0f / l2[0], inv1 = 1.0f / l2[1];
    int g = lane >> 2;
    int bb = bh >> 4, hh = bh & 15;
    int r_lo = q0 + w * 16 + g, r_hi = r_lo + 8;
    int cbase = hh * 64 + (lane & 3) * 2;
    #pragma unroll
    for (int nt = 0; nt < 8; nt++) {
        int cc = cbase + nt * 8;
        float v0 = acc_o[nt][0] * inv0, v1 = acc_o[nt][1] * inv0;
        float v2 = acc_o[nt][2] * inv1, v3 = acc_o[nt][3] * inv1;
        __nv_bfloat16 h0,lo0,h1,lo1,h2,lo2,h3,lo3;
        split_bf16(v0, h0, lo0); split_bf16(v1, h1, lo1);
        split_bf16(v2, h2, lo2); split_bf16(v3, h3, lo3);
        size_t off_lo = ((size_t)bb * SS + r_lo) * DD + cc;
        size_t off_hi = ((size_t)bb * SS + r_hi) * DD + cc;
        *(__nv_bfloat162*)(Oh + off_lo) = __nv_bfloat162(h0, h1);
        *(__nv_bfloat162*)(Ol + off_lo) = __nv_bfloat162(lo0, lo1);
        *(__nv_bfloat162*)(Oh + off_hi) = __nv_bfloat162(h2, h3);
        *(__nv_bfloat162*)(Ol + off_hi) = __nv_bfloat162(lo2, lo3);
    }
}

// ---------------- launch ----------------
extern "C" void kernel_launch(void* const* d_in, const int* in_sizes, int n_in,
                              void* d_out, int out_size)
{
    const float* x    = (const float*)d_in[0];
    const float* wq   = (const float*)d_in[1];
    const float* bq   = (const float*)d_in[2];
    const float* wk   = (const float*)d_in[3];
    const float* bk   = (const float*)d_in[4];
    const float* wv   = (const float*)d_in[5];
    const float* bv   = (const float*)d_in[6];
    const float* wo   = (const float*)d_in[7];
    const float* bo   = (const float*)d_in[8];
    const float* g1   = (const float*)d_in[9];
    const float* b1   = (const float*)d_in[10];
    const float* g2   = (const float*)d_in[11];
    const float* b2   = (const float*)d_in[12];
    const float* wfc1 = (const float*)d_in[13];
    const float* bfc1 = (const float*)d_in[14];
    const float* wfc2 = (const float*)d_in[15];
    const float* bfc2 = (const float*)d_in[16];
    float* out = (float*)d_out;

    float *o1;
    cudaGetSymbolAddress((void**)&o1, g_o1);
    __nv_bfloat16 *xh, *xl, *mh, *ml, *qh, *qlp, *kh, *kl, *vh, *vl;
    cudaGetSymbolAddress((void**)&xh, g_xh);
    cudaGetSymbolAddress((void**)&xl, g_xl);
    cudaGetSymbolAddress((void**)&mh, g_mh);
    cudaGetSymbolAddress((void**)&ml, g_ml);
    cudaGetSymbolAddress((void**)&qh, g_qh);
    cudaGetSymbolAddress((void**)&qlp, g_ql);
    cudaGetSymbolAddress((void**)&kh, g_kh);
    cudaGetSymbolAddress((void**)&kl, g_kl);
    cudaGetSymbolAddress((void**)&vh, g_vh);
    cudaGetSymbolAddress((void**)&vl, g_vl);
    __nv_bfloat16 *wqt, *wkt, *wvt, *wot, *w1t, *w2t;
    cudaGetSymbolAddress((void**)&wqt, g_wqt);
    cudaGetSymbolAddress((void**)&wkt, g_wkt);
    cudaGetSymbolAddress((void**)&wvt, g_wvt);
    cudaGetSymbolAddress((void**)&wot, g_wot);
    cudaGetSymbolAddress((void**)&w1t, g_w1t);
    cudaGetSymbolAddress((void**)&w2t, g_w2t);
    const size_t SQ = (size_t)DD * DD;
    const size_t SF = (size_t)DD * FFN;

    const int GEMM_SMEM = 2 * STG_SZ;  // 122880
    cudaFuncSetAttribute(gemm_mma<2>, cudaFuncAttributeMaxDynamicSharedMemorySize, GEMM_SMEM);
    cudaFuncSetAttribute(gemm_mma<3>, cudaFuncAttributeMaxDynamicSharedMemorySize, GEMM_SMEM);
    cudaFuncSetAttribute(gemm_mma<4>, cudaFuncAttributeMaxDynamicSharedMemorySize, GEMM_SMEM);
    cudaFuncSetAttribute(flash_mma, cudaFuncAttributeMaxDynamicSharedMemorySize, FLASH_SMEM);

    dim3 cb(32, 8);
    wconv<<<dim3(DD / 32, DD / 32), cb>>>(wq,   wqt, wqt + SQ, DD, DD);
    wconv<<<dim3(DD / 32, DD / 32), cb>>>(wk,   wkt, wkt + SQ, DD, DD);
    wconv<<<dim3(DD / 32, DD / 32), cb>>>(wv,   wvt, wvt + SQ, DD, DD);
    wconv<<<dim3(DD / 32, DD / 32), cb>>>(wo,   wot, wot + SQ, DD, DD);
    wconv<<<dim3(FFN / 32, DD / 32), cb>>>(wfc1, w1t, w1t + SF, DD, FFN);
    wconv<<<dim3(DD / 32, FFN / 32), cb>>>(wfc2, w2t, w2t + SF, FFN, DD);

    // 1. LN1 -> bf16 hi/lo
    layernorm_bf<<<ROWS, 256>>>(x, g1, b1, xh, xl);

    // 2. QKV projections -> (B,H,S,DH) bf16 hi/lo (Q pre-scaled by 1/32)
    dim3 gQKV(DD / 128, ROWS / 256);
    gemm_mma<4><<<gQKV, 256, GEMM_SMEM>>>(xh, xl, wqt, wqt + SQ, bq, nullptr, nullptr, qh, qlp, ROWS, DD, DD, 1.0f / 32.0f);
    gemm_mma<4><<<gQKV, 256, GEMM_SMEM>>>(xh, xl, wkt, wkt + SQ, bk, nullptr, nullptr, kh, kl,  ROWS, DD, DD, 1.0f);
    gemm_mma<4><<<gQKV, 256, GEMM_SMEM>>>(xh, xl, wvt, wvt + SQ, bv, nullptr, nullptr, vh, vl,  ROWS, DD, DD, 1.0f);

    // 3. attention -> bf16 hi/lo (B,S,D) into xh/xl
    flash_mma<<<dim3(SS / 128, BB * HH), 256, FLASH_SMEM>>>(qh, qlp, kh, kl, vh, vl, xh, xl);

    // 4. output projection + residual(x) -> o1 fp32
    gemm_mma<2><<<gQKV, 256, GEMM_SMEM>>>(xh, xl, wot, wot + SQ, bo, x, o1, nullptr, nullptr, ROWS, DD, DD, 1.0f);

    // 5. LN2 -> bf16 hi/lo
    layernorm_bf<<<ROWS, 256>>>(o1, g2, b2, xh, xl);

    // 6. FC1 + GELU -> bf16 hi/lo mid
    dim3 gFC1(FFN / 128, ROWS / 256);
    gemm_mma<3><<<gFC1, 256, GEMM_SMEM>>>(xh, xl, w1t, w1t + SF, bfc1, nullptr, nullptr, mh, ml, ROWS, FFN, DD, 1.0f);

    // 7. FC2 + residual(o1) -> out
    dim3 gFC2(DD / 128, ROWS / 256);
    gemm_mma<2><<<gFC2, 256, GEMM_SMEM>>>(mh, ml, w2t, w2t + SF, bfc2, o1, out, nullptr, nullptr, ROWS, DD, FFN, 1.0f);
}

// round 6
// speedup vs baseline: 1.5655x; 1.5655x over previous
#include <cuda_runtime.h>
#include <cuda_fp16.h>
#include <math.h>
#include <stdint.h>

// ---------------- problem constants ----------------
#define BB 4
#define SS 1024
#define DD 1024
#define HH 16
#define DHH 64
#define FFN 4096
#define ROWS (BB*SS)   // 4096

// ---------------- device scratch ----------------
__device__ float  g_o1 [ROWS*DD];
__device__ __half g_x  [ROWS*DD];               // LN out / attn out (single fp16)
__device__ __half g_mid[(size_t)ROWS*FFN];
__device__ __half g_q  [ROWS*DD];               // (B,H,S,DH)
__device__ __half g_k  [ROWS*DD];
__device__ __half g_v  [ROWS*DD];
// transposed fp16 weights: [0]=hi, [1]=lo, layout [N,K] K-major
__device__ __half g_wqt[2][DD*DD];
__device__ __half g_wkt[2][DD*DD];
__device__ __half g_wvt[2][DD*DD];
__device__ __half g_wot[2][DD*DD];
__device__ __half g_w1t[2][(size_t)DD*FFN];
__device__ __half g_w2t[2][(size_t)DD*FFN];

// ---------------- small helpers ----------------
__device__ __forceinline__ uint32_t smem_u32(const void* p) {
    uint32_t a;
    asm("{ .reg .u64 t; cvta.to.shared.u64 t, %1; cvt.u32.u64 %0, t; }" : "=r"(a) : "l"(p));
    return a;
}
__device__ __forceinline__ void cp_async16(uint32_t s, const void* g) {
    asm volatile("cp.async.cg.shared.global [%0], [%1], 16;" :: "r"(s), "l"(g));
}
__device__ __forceinline__ void ldsm_x4(uint32_t* r, uint32_t addr) {
    asm volatile("ldmatrix.sync.aligned.m8n8.x4.shared.b16 {%0,%1,%2,%3}, [%4];"
        : "=r"(r[0]), "=r"(r[1]), "=r"(r[2]), "=r"(r[3]) : "r"(addr));
}
__device__ __forceinline__ void ldsm_x4_t(uint32_t* r, uint32_t addr) {
    asm volatile("ldmatrix.sync.aligned.m8n8.x4.trans.shared.b16 {%0,%1,%2,%3}, [%4];"
        : "=r"(r[0]), "=r"(r[1]), "=r"(r[2]), "=r"(r[3]) : "r"(addr));
}
__device__ __forceinline__ void mma16816(float* d, const uint32_t* a, const uint32_t* b) {
    asm volatile("mma.sync.aligned.m16n8k16.row.col.f32.f16.f16.f32 "
        "{%0,%1,%2,%3}, {%4,%5,%6,%7}, {%8,%9}, {%0,%1,%2,%3};"
        : "+f"(d[0]), "+f"(d[1]), "+f"(d[2]), "+f"(d[3])
        : "r"(a[0]), "r"(a[1]), "r"(a[2]), "r"(a[3]), "r"(b[0]), "r"(b[1]));
}
__device__ __forceinline__ void split_f16(float v, __half& h, __half& l) {
    h = __float2half_rn(v);
    l = __float2half_rn(v - __half2float(h));
}
__device__ __forceinline__ uint32_t pack_h2(__half a, __half b) {
    __half2 t = __halves2half2(a, b);
    return *(uint32_t*)&t;
}

// ---------------- weight convert + transpose: W[K,N] fp32 -> [N,K] fp16 hi/lo ----
__global__ void wconv(const float* __restrict__ W, __half* __restrict__ Th,
                      __half* __restrict__ Tl, int K, int N)
{
    __shared__ float tile[32][33];
    int tx = threadIdx.x, ty = threadIdx.y;      // 32 x 8
    int n0 = blockIdx.x * 32, k0 = blockIdx.y * 32;
    #pragma unroll
    for (int i = 0; i < 4; i++)
        tile[ty + i*8][tx] = W[(size_t)(k0 + ty + i*8) * N + n0 + tx];
    __syncthreads();
    #pragma unroll
    for (int i = 0; i < 4; i++) {
        int n = n0 + ty + i*8;
        int k = k0 + tx;
        float v = tile[tx][ty + i*8];
        __half h, l; split_f16(v, h, l);
        Th[(size_t)n * K + k] = h;
        Tl[(size_t)n * K + k] = l;
    }
}

// ---------------- LayerNorm -> single fp16 ----------------
__global__ void layernorm_f16(const float* __restrict__ x, const float* __restrict__ g,
                              const float* __restrict__ b, __half* __restrict__ oh)
{
    __shared__ float red0[8], red1[8];
    int row = blockIdx.x, tid = threadIdx.x;
    const float4* xr = (const float4*)(x + (size_t)row * DD);
    float4 v = xr[tid];
    float s  = v.x + v.y + v.z + v.w;
    float s2 = v.x*v.x + v.y*v.y + v.z*v.z + v.w*v.w;
    #pragma unroll
    for (int o = 16; o; o >>= 1) {
        s  += __shfl_xor_sync(0xffffffffu, s,  o);
        s2 += __shfl_xor_sync(0xffffffffu, s2, o);
    }
    if ((tid & 31) == 0) { red0[tid >> 5] = s; red1[tid >> 5] = s2; }
    __syncthreads();
    float S = 0.f, S2 = 0.f;
    #pragma unroll
    for (int i = 0; i < 8; i++) { S += red0[i]; S2 += red1[i]; }
    float mean = S * (1.f / DD);
    float var  = S2 * (1.f / DD) - mean * mean;
    float rstd = rsqrtf(var + 1e-5f);
    float4 gv = ((const float4*)g)[tid];
    float4 bv = ((const float4*)b)[tid];
    float o0 = (v.x - mean) * rstd * gv.x + bv.x;
    float o1 = (v.y - mean) * rstd * gv.y + bv.y;
    float o2 = (v.z - mean) * rstd * gv.z + bv.z;
    float o3 = (v.w - mean) * rstd * gv.w + bv.w;
    size_t base = (size_t)row * DD + tid * 4;
    *(__half2*)(oh + base)     = __halves2half2(__float2half_rn(o0), __float2half_rn(o1));
    *(__half2*)(oh + base + 2) = __halves2half2(__float2half_rn(o2), __float2half_rn(o3));
}

// ---------------- tensor-core GEMM, fp16 2-pass: C = A*(Wh+Wl)^T + bias ----
// block 128x128, 8 warps (4m x 2n), warp tile 32x64, BK=32, double-buffered.
// smem per stage: A(10240) Bh(10240) Bl(10240) = 30720
// EPI 2: bias + residual -> fp32 C
// EPI 3: bias + GELU -> fp16 Ch
// EPI 4: (bias + val) * scl -> fp16 Ch scattered to (B,H,S,DH)
#define LDB 80
#define ARR 10240
#define STG_SZ 30720
template<int EPI>
__global__ void __launch_bounds__(256)
gemm_mma(const __half* __restrict__ A,
         const __half* __restrict__ Wh, const __half* __restrict__ Wl,
         const float* __restrict__ bias, const float* __restrict__ res,
         float* __restrict__ C, __half* __restrict__ Ch,
         int M, int N, int K, float scl)
{
    extern __shared__ char smem[];
    const uint32_t sb = smem_u32(smem);
    const int tid = threadIdx.x;
    const int wid = tid >> 5, lane = tid & 31;
    const int wm = wid & 3, wn = wid >> 2;
    const int m0 = blockIdx.y * 128, n0 = blockIdx.x * 128;

    float acc[2][8][4] = {};
    const int NK = K >> 5;

    auto load_stage = [&](int kc, int buf) {
        int k0 = kc << 5;
        uint32_t stb = sb + buf * STG_SZ;
        #pragma unroll
        for (int i = 0; i < 6; i++) {
            int c = tid + i * 256;        // 0..1535
            int arr = c >> 9;             // 0:A 1:Bh 2:Bl
            int cc = c & 511;
            int row = cc >> 2, col = cc & 3;
            const __half* gsrc;
            if      (arr == 0) gsrc = A  + (size_t)(m0 + row) * K + k0 + col * 8;
            else if (arr == 1) gsrc = Wh + (size_t)(n0 + row) * K + k0 + col * 8;
            else               gsrc = Wl + (size_t)(n0 + row) * K + k0 + col * 8;
            cp_async16(stb + arr * ARR + row * LDB + col * 16, gsrc);
        }
        asm volatile("cp.async.commit_group;" ::: "memory");
    };

    load_stage(0, 0);

    for (int kc = 0; kc < NK; kc++) {
        int buf = kc & 1;
        if (kc + 1 < NK) {
            load_stage(kc + 1, buf ^ 1);
            asm volatile("cp.async.wait_group 1;" ::: "memory");
        } else {
            asm volatile("cp.async.wait_group 0;" ::: "memory");
        }
        __syncthreads();

        uint32_t stb = sb + buf * STG_SZ;
        #pragma unroll
        for (int ks = 0; ks < 2; ks++) {
            uint32_t Af[2][4], Bf[8][2];
            int ar = lane & 15, ac = ks * 16 + (lane >> 4) * 8;
            #pragma unroll
            for (int mt = 0; mt < 2; mt++)
                ldsm_x4(Af[mt], stb + (wm * 32 + mt * 16 + ar) * LDB + ac * 2);
            int gq = lane >> 3, l8 = lane & 7;
            int br = (gq >> 1) * 8 + l8, bc = ks * 16 + (gq & 1) * 8;
            // --- B hi ---
            #pragma unroll
            for (int p = 0; p < 4; p++) {
                uint32_t a = stb + ARR + (wn * 64 + p * 16 + br) * LDB + bc * 2;
                uint32_t t[4];
                ldsm_x4(t, a);
                Bf[2*p][0] = t[0]; Bf[2*p][1] = t[1];
                Bf[2*p+1][0] = t[2]; Bf[2*p+1][1] = t[3];
            }
            #pragma unroll
            for (int mt = 0; mt < 2; mt++)
                #pragma unroll
                for (int nt = 0; nt < 8; nt++)
                    mma16816(acc[mt][nt], Af[mt], Bf[nt]);
            // --- B lo ---
            #pragma unroll
            for (int p = 0; p < 4; p++) {
                uint32_t a = stb + 2 * ARR + (wn * 64 + p * 16 + br) * LDB + bc * 2;
                uint32_t t[4];
                ldsm_x4(t, a);
                Bf[2*p][0] = t[0]; Bf[2*p][1] = t[1];
                Bf[2*p+1][0] = t[2]; Bf[2*p+1][1] = t[3];
            }
            #pragma unroll
            for (int mt = 0; mt < 2; mt++)
                #pragma unroll
                for (int nt = 0; nt < 8; nt++)
                    mma16816(acc[mt][nt], Af[mt], Bf[nt]);
        }
        __syncthreads();
    }

    // ---- epilogue ----
    int rb = m0 + wm * 32 + (lane >> 2);
    int cb = n0 + wn * 64 + (lane & 3) * 2;
    #pragma unroll
    for (int mt = 0; mt < 2; mt++) {
        #pragma unroll
        for (int half = 0; half < 2; half++) {
            int r = rb + mt * 16 + half * 8;
            #pragma unroll
            for (int nt = 0; nt < 8; nt++) {
                int n = cb + nt * 8;
                float2 bv = *(const float2*)(bias + n);
                float v0 = acc[mt][nt][half * 2 + 0] + bv.x;
                float v1 = acc[mt][nt][half * 2 + 1] + bv.y;
                if (EPI == 2) {
                    float2 rv = *(const float2*)(res + (size_t)r * N + n);
                    v0 += rv.x; v1 += rv.y;
                    *(float2*)(C + (size_t)r * N + n) = make_float2(v0, v1);
                } else if (EPI == 3) {
                    v0 = 0.5f * v0 * (1.0f + erff(v0 * 0.70710678118654752f));
                    v1 = 0.5f * v1 * (1.0f + erff(v1 * 0.70710678118654752f));
                    *(__half2*)(Ch + (size_t)r * N + n) =
                        __halves2half2(__float2half_rn(v0), __float2half_rn(v1));
                } else if (EPI == 4) {
                    v0 *= scl; v1 *= scl;
                    int b_ = r >> 10, s = r & 1023, hh = n >> 6, dh = n & 63;
                    size_t off = ((size_t)(b_ * HH + hh) * SS + s) * DHH + dh;
                    *(__half2*)(Ch + off) =
                        __halves2half2(__float2half_rn(v0), __float2half_rn(v1));
                }
            }
        }
    }
}

// ---------------- Flash attention via mma.sync, fp16 single, 1-pass -------
// BQ=128, BK=64, DH=64; 8 warps, each owns 16 Q rows.
#define LDK 144
#define FQ_SZ 18432           // 128 rows * 144
#define FST0  18432
#define FARR  9216            // 64 rows * 144
#define FST_SZ 18432          // Kh + Vh
#define FLASH_SMEM (FST0 + 2*FST_SZ)   // 55296
__global__ void __launch_bounds__(256)
flash_mma(const __half* __restrict__ Q_, const __half* __restrict__ K_,
          const __half* __restrict__ V_, __half* __restrict__ O_)
{
    extern __shared__ char smc[];
    const uint32_t sb = smem_u32(smc);
    int tid = threadIdx.x, lane = tid & 31, w = tid >> 5;
    int bh = blockIdx.y, q0 = blockIdx.x * 128;
    size_t qbase = ((size_t)bh * SS + q0) * DHH;
    size_t kvbase = (size_t)bh * SS * DHH;

    // Q -> smem (128x64 fp16 = 1024 cp16)
    #pragma unroll
    for (int i = 0; i < 4; i++) {
        int c = tid + i * 256;
        int row = c >> 3, col = c & 7;
        cp_async16(sb + row * LDK + col * 16, Q_ + qbase + row * 64 + col * 8);
    }
    auto load_stage = [&](int t, int buf) {
        size_t base = kvbase + (size_t)t * 64 * DHH;
        #pragma unroll
        for (int i = 0; i < 4; i++) {
            int c = tid + i * 256;       // 0..1023
            int arr = c >> 9, cc = c & 511;
            int row = cc >> 3, col = cc & 7;
            const __half* src = (arr ? V_ : K_) + base + row * 64 + col * 8;
            cp_async16(sb + FST0 + buf * FST_SZ + arr * FARR + row * LDK + col * 16, src);
        }
    };
    load_stage(0, 0);
    asm volatile("cp.async.commit_group;" ::: "memory");

    uint32_t qf[4][4];
    float m2[2] = {-1e30f, -1e30f}, l2[2] = {0.f, 0.f};
    float acc_o[8][4] = {};

    for (int t = 0; t < SS / 64; t++) {
        int buf = t & 1;
        if (t + 1 < SS / 64) {
            load_stage(t + 1, (t + 1) & 1);
            asm volatile("cp.async.commit_group;" ::: "memory");
            asm volatile("cp.async.wait_group 1;" ::: "memory");
        } else {
            asm volatile("cp.async.wait_group 0;" ::: "memory");
        }
        __syncthreads();
        if (t == 0) {
            #pragma unroll
            for (int ks = 0; ks < 4; ks++)
                ldsm_x4(qf[ks], sb + (w * 16 + (lane & 15)) * LDK + ks * 32 + (lane >> 4) * 16);
        }
        uint32_t stb = sb + FST0 + buf * FST_SZ;

        // ---- S = Q K^T (1 pass) ----
        float s[8][4] = {};
        int gq = lane >> 3, l8 = lane & 7;
        int br = (gq >> 1) * 8 + l8;
        #pragma unroll
        for (int ks = 0; ks < 4; ks++) {
            uint32_t Bf[8][2];
            int bcB = ks * 32 + (gq & 1) * 16;
            #pragma unroll
            for (int p = 0; p < 4; p++) {
                uint32_t a = stb + (p * 16 + br) * LDK + bcB;
                uint32_t t4[4];
                ldsm_x4(t4, a);
                Bf[2*p][0] = t4[0]; Bf[2*p][1] = t4[1];
                Bf[2*p+1][0] = t4[2]; Bf[2*p+1][1] = t4[3];
            }
            #pragma unroll
            for (int nt = 0; nt < 8; nt++)
                mma16816(s[nt], qf[ks], Bf[nt]);
        }

        // ---- online softmax ----
        float rm0 = -1e30f, rm1 = -1e30f;
        #pragma unroll
        for (int nt = 0; nt < 8; nt++) {
            rm0 = fmaxf(rm0, fmaxf(s[nt][0], s[nt][1]));
            rm1 = fmaxf(rm1, fmaxf(s[nt][2], s[nt][3]));
        }
        rm0 = fmaxf(rm0, __shfl_xor_sync(0xffffffffu, rm0, 1));
        rm0 = fmaxf(rm0, __shfl_xor_sync(0xffffffffu, rm0, 2));
        rm1 = fmaxf(rm1, __shfl_xor_sync(0xffffffffu, rm1, 1));
        rm1 = fmaxf(rm1, __shfl_xor_sync(0xffffffffu, rm1, 2));
        float mn0 = fmaxf(m2[0], rm0), mn1 = fmaxf(m2[1], rm1);
        float al0 = __expf(m2[0] - mn0), al1 = __expf(m2[1] - mn1);
        float rs0 = 0.f, rs1 = 0.f;
        #pragma unroll
        for (int nt = 0; nt < 8; nt++) {
            s[nt][0] = __expf(s[nt][0] - mn0);
            s[nt][1] = __expf(s[nt][1] - mn0);
            s[nt][2] = __expf(s[nt][2] - mn1);
            s[nt][3] = __expf(s[nt][3] - mn1);
            rs0 += s[nt][0] + s[nt][1];
            rs1 += s[nt][2] + s[nt][3];
        }
        rs0 += __shfl_xor_sync(0xffffffffu, rs0, 1);
        rs0 += __shfl_xor_sync(0xffffffffu, rs0, 2);
        rs1 += __shfl_xor_sync(0xffffffffu, rs1, 1);
        rs1 += __shfl_xor_sync(0xffffffffu, rs1, 2);
        l2[0] = l2[0] * al0 + rs0;
        l2[1] = l2[1] * al1 + rs1;
        m2[0] = mn0; m2[1] = mn1;
        #pragma unroll
        for (int nt = 0; nt < 8; nt++) {
            acc_o[nt][0] *= al0; acc_o[nt][1] *= al0;
            acc_o[nt][2] *= al1; acc_o[nt][3] *= al1;
        }

        // ---- O += P V (1 pass) ----
        int vr = ((lane >> 3) & 1) * 8 + (lane & 7);
        int vcb = ((lane >> 4) * 8) * 2;
        #pragma unroll
        for (int ks = 0; ks < 4; ks++) {
            uint32_t pf[4];
            #pragma unroll
            for (int q2 = 0; q2 < 2; q2++) {
                pf[2*q2]     = pack_h2(__float2half_rn(s[2*ks + q2][0]), __float2half_rn(s[2*ks + q2][1]));
                pf[2*q2 + 1] = pack_h2(__float2half_rn(s[2*ks + q2][2]), __float2half_rn(s[2*ks + q2][3]));
            }
            uint32_t Vf[8][2];
            #pragma unroll
            for (int np = 0; np < 4; np++) {
                uint32_t a = stb + FARR + (ks * 16 + vr) * LDK + np * 32 + vcb;
                uint32_t t4[4];
                ldsm_x4_t(t4, a);
                Vf[2*np][0] = t4[0]; Vf[2*np][1] = t4[1];
                Vf[2*np+1][0] = t4[2]; Vf[2*np+1][1] = t4[3];
            }
            #pragma unroll
            for (int nt = 0; nt < 8; nt++)
                mma16816(acc_o[nt], pf, Vf[nt]);
        }
        __syncthreads();
    }

    // ---- epilogue: O/l -> fp16, (B,S,D) layout ----
    float inv0 = 1.0f / l2[0], inv1 = 1.0f / l2[1];
    int g = lane >> 2;
    int bb = bh >> 4, hh = bh & 15;
    int r_lo = q0 + w * 16 + g, r_hi = r_lo + 8;
    int cbase = hh * 64 + (lane & 3) * 2;
    #pragma unroll
    for (int nt = 0; nt < 8; nt++) {
        int cc = cbase + nt * 8;
        size_t off_lo = ((size_t)bb * SS + r_lo) * DD + cc;
        size_t off_hi = ((size_t)bb * SS + r_hi) * DD + cc;
        *(__half2*)(O_ + off_lo) = __halves2half2(
            __float2half_rn(acc_o[nt][0] * inv0), __float2half_rn(acc_o[nt][1] * inv0));
        *(__half2*)(O_ + off_hi) = __halves2half2(
            __float2half_rn(acc_o[nt][2] * inv1), __float2half_rn(acc_o[nt][3] * inv1));
    }
}

// ---------------- launch ----------------
extern "C" void kernel_launch(void* const* d_in, const int* in_sizes, int n_in,
                              void* d_out, int out_size)
{
    const float* x    = (const float*)d_in[0];
    const float* wq   = (const float*)d_in[1];
    const float* bq   = (const float*)d_in[2];
    const float* wk   = (const float*)d_in[3];
    const float* bk   = (const float*)d_in[4];
    const float* wv   = (const float*)d_in[5];
    const float* bv   = (const float*)d_in[6];
    const float* wo   = (const float*)d_in[7];
    const float* bo   = (const float*)d_in[8];
    const float* g1   = (const float*)d_in[9];
    const float* b1   = (const float*)d_in[10];
    const float* g2   = (const float*)d_in[11];
    const float* b2   = (const float*)d_in[12];
    const float* wfc1 = (const float*)d_in[13];
    const float* bfc1 = (const float*)d_in[14];
    const float* wfc2 = (const float*)d_in[15];
    const float* bfc2 = (const float*)d_in[16];
    float* out = (float*)d_out;

    float *o1;
    cudaGetSymbolAddress((void**)&o1, g_o1);
    __half *xa, *mid, *q, *k, *v;
    cudaGetSymbolAddress((void**)&xa,  g_x);
    cudaGetSymbolAddress((void**)&mid, g_mid);
    cudaGetSymbolAddress((void**)&q,   g_q);
    cudaGetSymbolAddress((void**)&k,   g_k);
    cudaGetSymbolAddress((void**)&v,   g_v);
    __half *wqt, *wkt, *wvt, *wot, *w1t, *w2t;
    cudaGetSymbolAddress((void**)&wqt, g_wqt);
    cudaGetSymbolAddress((void**)&wkt, g_wkt);
    cudaGetSymbolAddress((void**)&wvt, g_wvt);
    cudaGetSymbolAddress((void**)&wot, g_wot);
    cudaGetSymbolAddress((void**)&w1t, g_w1t);
    cudaGetSymbolAddress((void**)&w2t, g_w2t);
    const size_t SQ = (size_t)DD * DD;
    const size_t SF = (size_t)DD * FFN;

    const int GEMM_SMEM = 2 * STG_SZ;  // 61440
    cudaFuncSetAttribute(gemm_mma<2>, cudaFuncAttributeMaxDynamicSharedMemorySize, GEMM_SMEM);
    cudaFuncSetAttribute(gemm_mma<3>, cudaFuncAttributeMaxDynamicSharedMemorySize, GEMM_SMEM);
    cudaFuncSetAttribute(gemm_mma<4>, cudaFuncAttributeMaxDynamicSharedMemorySize, GEMM_SMEM);
    cudaFuncSetAttribute(flash_mma, cudaFuncAttributeMaxDynamicSharedMemorySize, FLASH_SMEM);

    dim3 cb(32, 8);
    wconv<<<dim3(DD / 32, DD / 32), cb>>>(wq,   wqt, wqt + SQ, DD, DD);
    wconv<<<dim3(DD / 32, DD / 32), cb>>>(wk,   wkt, wkt + SQ, DD, DD);
    wconv<<<dim3(DD / 32, DD / 32), cb>>>(wv,   wvt, wvt + SQ, DD, DD);
    wconv<<<dim3(DD / 32, DD / 32), cb>>>(wo,   wot, wot + SQ, DD, DD);
    wconv<<<dim3(FFN / 32, DD / 32), cb>>>(wfc1, w1t, w1t + SF, DD, FFN);
    wconv<<<dim3(DD / 32, FFN / 32), cb>>>(wfc2, w2t, w2t + SF, FFN, DD);

    // 1. LN1 -> fp16
    layernorm_f16<<<ROWS, 256>>>(x, g1, b1, xa);

    // 2. QKV projections -> (B,H,S,DH) fp16 (Q pre-scaled by 1/32)
    dim3 gQKV(DD / 128, ROWS / 128);
    gemm_mma<4><<<gQKV, 256, GEMM_SMEM>>>(xa, wqt, wqt + SQ, bq, nullptr, nullptr, q, ROWS, DD, DD, 1.0f / 32.0f);
    gemm_mma<4><<<gQKV, 256, GEMM_SMEM>>>(xa, wkt, wkt + SQ, bk, nullptr, nullptr, k, ROWS, DD, DD, 1.0f);
    gemm_mma<4><<<gQKV, 256, GEMM_SMEM>>>(xa, wvt, wvt + SQ, bv, nullptr, nullptr, v, ROWS, DD, DD, 1.0f);

    // 3. attention -> fp16 (B,S,D) into xa
    flash_mma<<<dim3(SS / 128, BB * HH), 256, FLASH_SMEM>>>(q, k, v, xa);

    // 4. output projection + residual(x) -> o1 fp32
    gemm_mma<2><<<gQKV, 256, GEMM_SMEM>>>(xa, wot, wot + SQ, bo, x, o1, nullptr, ROWS, DD, DD, 1.0f);

    // 5. LN2 -> fp16
    layernorm_f16<<<ROWS, 256>>>(o1, g2, b2, xa);

    // 6. FC1 + GELU -> fp16 mid
    dim3 gFC1(FFN / 128, ROWS / 128);
    gemm_mma<3><<<gFC1, 256, GEMM_SMEM>>>(xa, w1t, w1t + SF, bfc1, nullptr, nullptr, mid, ROWS, FFN, DD, 1.0f);

    // 7. FC2 + residual(o1) -> out
    dim3 gFC2(DD / 128, ROWS / 128);
    gemm_mma<2><<<gFC2, 256, GEMM_SMEM>>>(mid, w2t, w2t + SF, bfc2, o1, out, nullptr, ROWS, DD, FFN, 1.0f);
}

// round 7
// speedup vs baseline: 2.3308x; 1.4889x over previous
#include <cuda_runtime.h>
#include <cuda_fp16.h>
#include <math.h>
#include <stdint.h>

// ---------------- problem constants ----------------
#define BB 4
#define SS 1024
#define DD 1024
#define HH 16
#define DHH 64
#define FFN 4096
#define ROWS (BB*SS)   // 4096

// ---------------- device scratch ----------------
__device__ float  g_o1 [ROWS*DD];
__device__ __half g_x  [ROWS*DD];               // LN out / attn out (single fp16)
__device__ __half g_mid[(size_t)ROWS*FFN];
__device__ __half g_q  [ROWS*DD];               // (B,H,S,DH)
__device__ __half g_k  [ROWS*DD];
__device__ __half g_v  [ROWS*DD];
// transposed fp16 weights, layout [N,K] K-major
__device__ __half g_wqt[DD*DD];
__device__ __half g_wkt[DD*DD];
__device__ __half g_wvt[DD*DD];
__device__ __half g_wot[DD*DD];
__device__ __half g_w1t[(size_t)DD*FFN];
__device__ __half g_w2t[(size_t)DD*FFN];

// ---------------- small helpers ----------------
__device__ __forceinline__ uint32_t smem_u32(const void* p) {
    uint32_t a;
    asm("{ .reg .u64 t; cvta.to.shared.u64 t, %1; cvt.u32.u64 %0, t; }" : "=r"(a) : "l"(p));
    return a;
}
__device__ __forceinline__ void cp_async16(uint32_t s, const void* g) {
    asm volatile("cp.async.cg.shared.global [%0], [%1], 16;" :: "r"(s), "l"(g));
}
__device__ __forceinline__ void ldsm_x4(uint32_t* r, uint32_t addr) {
    asm volatile("ldmatrix.sync.aligned.m8n8.x4.shared.b16 {%0,%1,%2,%3}, [%4];"
        : "=r"(r[0]), "=r"(r[1]), "=r"(r[2]), "=r"(r[3]) : "r"(addr));
}
__device__ __forceinline__ void ldsm_x4_t(uint32_t* r, uint32_t addr) {
    asm volatile("ldmatrix.sync.aligned.m8n8.x4.trans.shared.b16 {%0,%1,%2,%3}, [%4];"
        : "=r"(r[0]), "=r"(r[1]), "=r"(r[2]), "=r"(r[3]) : "r"(addr));
}
__device__ __forceinline__ void mma16816(float* d, const uint32_t* a, const uint32_t* b) {
    asm volatile("mma.sync.aligned.m16n8k16.row.col.f32.f16.f16.f32 "
        "{%0,%1,%2,%3}, {%4,%5,%6,%7}, {%8,%9}, {%0,%1,%2,%3};"
        : "+f"(d[0]), "+f"(d[1]), "+f"(d[2]), "+f"(d[3])
        : "r"(a[0]), "r"(a[1]), "r"(a[2]), "r"(a[3]), "r"(b[0]), "r"(b[1]));
}
__device__ __forceinline__ uint32_t pack_h2(__half a, __half b) {
    __half2 t = __halves2half2(a, b);
    return *(uint32_t*)&t;
}

// ---------------- weight convert + transpose: W[K,N] fp32 -> [N,K] fp16 ----
__global__ void wconv(const float* __restrict__ W, __half* __restrict__ Th, int K, int N)
{
    __shared__ float tile[32][33];
    int tx = threadIdx.x, ty = threadIdx.y;      // 32 x 8
    int n0 = blockIdx.x * 32, k0 = blockIdx.y * 32;
    #pragma unroll
    for (int i = 0; i < 4; i++)
        tile[ty + i*8][tx] = W[(size_t)(k0 + ty + i*8) * N + n0 + tx];
    __syncthreads();
    #pragma unroll
    for (int i = 0; i < 4; i++) {
        int n = n0 + ty + i*8;
        int k = k0 + tx;
        Th[(size_t)n * K + k] = __float2half_rn(tile[tx][ty + i*8]);
    }
}

// ---------------- LayerNorm -> single fp16 ----------------
__global__ void layernorm_f16(const float* __restrict__ x, const float* __restrict__ g,
                              const float* __restrict__ b, __half* __restrict__ oh)
{
    __shared__ float red0[8], red1[8];
    int row = blockIdx.x, tid = threadIdx.x;
    const float4* xr = (const float4*)(x + (size_t)row * DD);
    float4 v = xr[tid];
    float s  = v.x + v.y + v.z + v.w;
    float s2 = v.x*v.x + v.y*v.y + v.z*v.z + v.w*v.w;
    #pragma unroll
    for (int o = 16; o; o >>= 1) {
        s  += __shfl_xor_sync(0xffffffffu, s,  o);
        s2 += __shfl_xor_sync(0xffffffffu, s2, o);
    }
    if ((tid & 31) == 0) { red0[tid >> 5] = s; red1[tid >> 5] = s2; }
    __syncthreads();
    float S = 0.f, S2 = 0.f;
    #pragma unroll
    for (int i = 0; i < 8; i++) { S += red0[i]; S2 += red1[i]; }
    float mean = S * (1.f / DD);
    float var  = S2 * (1.f / DD) - mean * mean;
    float rstd = rsqrtf(var + 1e-5f);
    float4 gv = ((const float4*)g)[tid];
    float4 bv = ((const float4*)b)[tid];
    float o0 = (v.x - mean) * rstd * gv.x + bv.x;
    float o1 = (v.y - mean) * rstd * gv.y + bv.y;
    float o2 = (v.z - mean) * rstd * gv.z + bv.z;
    float o3 = (v.w - mean) * rstd * gv.w + bv.w;
    size_t base = (size_t)row * DD + tid * 4;
    *(__half2*)(oh + base)     = __halves2half2(__float2half_rn(o0), __float2half_rn(o1));
    *(__half2*)(oh + base + 2) = __halves2half2(__float2half_rn(o2), __float2half_rn(o3));
}

// ---------------- tensor-core GEMM, fp16 1-pass: C = A*W^T + bias ---------
// block 128x128, 8 warps (4m x 2n), warp tile 32x64, BK=32, double-buffered.
// smem per stage: A(10240) + B(10240) = 20480
// EPI 2: bias + residual -> fp32 C
// EPI 3: bias + GELU -> fp16 Ch
// EPI 4: (bias + val) * scl -> fp16 Ch scattered to (B,H,S,DH)
#define LDB 80
#define ARR 10240
#define STG_SZ 20480
template<int EPI>
__global__ void __launch_bounds__(256)
gemm_mma(const __half* __restrict__ A, const __half* __restrict__ W,
         const float* __restrict__ bias, const float* __restrict__ res,
         float* __restrict__ C, __half* __restrict__ Ch,
         int M, int N, int K, float scl)
{
    extern __shared__ char smem[];
    const uint32_t sb = smem_u32(smem);
    const int tid = threadIdx.x;
    const int wid = tid >> 5, lane = tid & 31;
    const int wm = wid & 3, wn = wid >> 2;
    const int m0 = blockIdx.y * 128, n0 = blockIdx.x * 128;

    float acc[2][8][4] = {};
    const int NK = K >> 5;

    auto load_stage = [&](int kc, int buf) {
        int k0 = kc << 5;
        uint32_t stb = sb + buf * STG_SZ;
        #pragma unroll
        for (int i = 0; i < 4; i++) {
            int c = tid + i * 256;        // 0..1023
            int arr = c >> 9;             // 0:A 1:B
            int cc = c & 511;
            int row = cc >> 2, col = cc & 3;
            const __half* gsrc = (arr ? W + (size_t)(n0 + row) * K
                                      : A + (size_t)(m0 + row) * K) + k0 + col * 8;
            cp_async16(stb + arr * ARR + row * LDB + col * 16, gsrc);
        }
        asm volatile("cp.async.commit_group;" ::: "memory");
    };

    load_stage(0, 0);

    for (int kc = 0; kc < NK; kc++) {
        int buf = kc & 1;
        if (kc + 1 < NK) {
            load_stage(kc + 1, buf ^ 1);
            asm volatile("cp.async.wait_group 1;" ::: "memory");
        } else {
            asm volatile("cp.async.wait_group 0;" ::: "memory");
        }
        __syncthreads();

        uint32_t stb = sb + buf * STG_SZ;
        #pragma unroll
        for (int ks = 0; ks < 2; ks++) {
            uint32_t Af[2][4], Bf[8][2];
            int ar = lane & 15, ac = ks * 16 + (lane >> 4) * 8;
            #pragma unroll
            for (int mt = 0; mt < 2; mt++)
                ldsm_x4(Af[mt], stb + (wm * 32 + mt * 16 + ar) * LDB + ac * 2);
            int gq = lane >> 3, l8 = lane & 7;
            int br = (gq >> 1) * 8 + l8, bc = ks * 16 + (gq & 1) * 8;
            #pragma unroll
            for (int p = 0; p < 4; p++) {
                uint32_t a = stb + ARR + (wn * 64 + p * 16 + br) * LDB + bc * 2;
                uint32_t t[4];
                ldsm_x4(t, a);
                Bf[2*p][0] = t[0]; Bf[2*p][1] = t[1];
                Bf[2*p+1][0] = t[2]; Bf[2*p+1][1] = t[3];
            }
            #pragma unroll
            for (int mt = 0; mt < 2; mt++)
                #pragma unroll
                for (int nt = 0; nt < 8; nt++)
                    mma16816(acc[mt][nt], Af[mt], Bf[nt]);
        }
        __syncthreads();
    }

    // ---- epilogue ----
    int rb = m0 + wm * 32 + (lane >> 2);
    int cb = n0 + wn * 64 + (lane & 3) * 2;
    #pragma unroll
    for (int mt = 0; mt < 2; mt++) {
        #pragma unroll
        for (int half = 0; half < 2; half++) {
            int r = rb + mt * 16 + half * 8;
            #pragma unroll
            for (int nt = 0; nt < 8; nt++) {
                int n = cb + nt * 8;
                float2 bv = *(const float2*)(bias + n);
                float v0 = acc[mt][nt][half * 2 + 0] + bv.x;
                float v1 = acc[mt][nt][half * 2 + 1] + bv.y;
                if (EPI == 2) {
                    float2 rv = *(const float2*)(res + (size_t)r * N + n);
                    v0 += rv.x; v1 += rv.y;
                    *(float2*)(C + (size_t)r * N + n) = make_float2(v0, v1);
                } else if (EPI == 3) {
                    v0 = 0.5f * v0 * (1.0f + erff(v0 * 0.70710678118654752f));
                    v1 = 0.5f * v1 * (1.0f + erff(v1 * 0.70710678118654752f));
                    *(__half2*)(Ch + (size_t)r * N + n) =
                        __halves2half2(__float2half_rn(v0), __float2half_rn(v1));
                } else if (EPI == 4) {
                    v0 *= scl; v1 *= scl;
                    int b_ = r >> 10, s = r & 1023, hh = n >> 6, dh = n & 63;
                    size_t off = ((size_t)(b_ * HH + hh) * SS + s) * DHH + dh;
                    *(__half2*)(Ch + off) =
                        __halves2half2(__float2half_rn(v0), __float2half_rn(v1));
                }
            }
        }
    }
}

// ---------------- Flash attention via mma.sync, fp16, 1-pass --------------
// BQ=128, BK=64, DH=64; 8 warps, each owns 16 Q rows.
#define LDK 144
#define FQ_SZ 18432
#define FST0  18432
#define FARR  9216
#define FST_SZ 18432
#define FLASH_SMEM (FST0 + 2*FST_SZ)   // 55296
__global__ void __launch_bounds__(256)
flash_mma(const __half* __restrict__ Q_, const __half* __restrict__ K_,
          const __half* __restrict__ V_, __half* __restrict__ O_)
{
    extern __shared__ char smc[];
    const uint32_t sb = smem_u32(smc);
    int tid = threadIdx.x, lane = tid & 31, w = tid >> 5;
    int bh = blockIdx.y, q0 = blockIdx.x * 128;
    size_t qbase = ((size_t)bh * SS + q0) * DHH;
    size_t kvbase = (size_t)bh * SS * DHH;

    #pragma unroll
    for (int i = 0; i < 4; i++) {
        int c = tid + i * 256;
        int row = c >> 3, col = c & 7;
        cp_async16(sb + row * LDK + col * 16, Q_ + qbase + row * 64 + col * 8);
    }
    auto load_stage = [&](int t, int buf) {
        size_t base = kvbase + (size_t)t * 64 * DHH;
        #pragma unroll
        for (int i = 0; i < 4; i++) {
            int c = tid + i * 256;
            int arr = c >> 9, cc = c & 511;
            int row = cc >> 3, col = cc & 7;
            const __half* src = (arr ? V_ : K_) + base + row * 64 + col * 8;
            cp_async16(sb + FST0 + buf * FST_SZ + arr * FARR + row * LDK + col * 16, src);
        }
    };
    load_stage(0, 0);
    asm volatile("cp.async.commit_group;" ::: "memory");

    uint32_t qf[4][4];
    float m2[2] = {-1e30f, -1e30f}, l2[2] = {0.f, 0.f};
    float acc_o[8][4] = {};

    for (int t = 0; t < SS / 64; t++) {
        int buf = t & 1;
        if (t + 1 < SS / 64) {
            load_stage(t + 1, (t + 1) & 1);
            asm volatile("cp.async.commit_group;" ::: "memory");
            asm volatile("cp.async.wait_group 1;" ::: "memory");
        } else {
            asm volatile("cp.async.wait_group 0;" ::: "memory");
        }
        __syncthreads();
        if (t == 0) {
            #pragma unroll
            for (int ks = 0; ks < 4; ks++)
                ldsm_x4(qf[ks], sb + (w * 16 + (lane & 15)) * LDK + ks * 32 + (lane >> 4) * 16);
        }
        uint32_t stb = sb + FST0 + buf * FST_SZ;

        float s[8][4] = {};
        int gq = lane >> 3, l8 = lane & 7;
        int br = (gq >> 1) * 8 + l8;
        #pragma unroll
        for (int ks = 0; ks < 4; ks++) {
            uint32_t Bf[8][2];
            int bcB = ks * 32 + (gq & 1) * 16;
            #pragma unroll
            for (int p = 0; p < 4; p++) {
                uint32_t a = stb + (p * 16 + br) * LDK + bcB;
                uint32_t t4[4];
                ldsm_x4(t4, a);
                Bf[2*p][0] = t4[0]; Bf[2*p][1] = t4[1];
                Bf[2*p+1][0] = t4[2]; Bf[2*p+1][1] = t4[3];
            }
            #pragma unroll
            for (int nt = 0; nt < 8; nt++)
                mma16816(s[nt], qf[ks], Bf[nt]);
        }

        float rm0 = -1e30f, rm1 = -1e30f;
        #pragma unroll
        for (int nt = 0; nt < 8; nt++) {
            rm0 = fmaxf(rm0, fmaxf(s[nt][0], s[nt][1]));
            rm1 = fmaxf(rm1, fmaxf(s[nt][2], s[nt][3]));
        }
        rm0 = fmaxf(rm0, __shfl_xor_sync(0xffffffffu, rm0, 1));
        rm0 = fmaxf(rm0, __shfl_xor_sync(0xffffffffu, rm0, 2));
        rm1 = fmaxf(rm1, __shfl_xor_sync(0xffffffffu, rm1, 1));
        rm1 = fmaxf(rm1, __shfl_xor_sync(0xffffffffu, rm1, 2));
        float mn0 = fmaxf(m2[0], rm0), mn1 = fmaxf(m2[1], rm1);
        float al0 = __expf(m2[0] - mn0), al1 = __expf(m2[1] - mn1);
        float rs0 = 0.f, rs1 = 0.f;
        #pragma unroll
        for (int nt = 0; nt < 8; nt++) {
            s[nt][0] = __expf(s[nt][0] - mn0);
            s[nt][1] = __expf(s[nt][1] - mn0);
            s[nt][2] = __expf(s[nt][2] - mn1);
            s[nt][3] = __expf(s[nt][3] - mn1);
            rs0 += s[nt][0] + s[nt][1];
            rs1 += s[nt][2] + s[nt][3];
        }
        rs0 += __shfl_xor_sync(0xffffffffu, rs0, 1);
        rs0 += __shfl_xor_sync(0xffffffffu, rs0, 2);
        rs1 += __shfl_xor_sync(0xffffffffu, rs1, 1);
        rs1 += __shfl_xor_sync(0xffffffffu, rs1, 2);
        l2[0] = l2[0] * al0 + rs0;
        l2[1] = l2[1] * al1 + rs1;
        m2[0] = mn0; m2[1] = mn1;
        #pragma unroll
        for (int nt = 0; nt < 8; nt++) {
            acc_o[nt][0] *= al0; acc_o[nt][1] *= al0;
            acc_o[nt][2] *= al1; acc_o[nt][3] *= al1;
        }

        int vr = ((lane >> 3) & 1) * 8 + (lane & 7);
        int vcb = ((lane >> 4) * 8) * 2;
        #pragma unroll
        for (int ks = 0; ks < 4; ks++) {
            uint32_t pf[4];
            #pragma unroll
            for (int q2 = 0; q2 < 2; q2++) {
                pf[2*q2]     = pack_h2(__float2half_rn(s[2*ks + q2][0]), __float2half_rn(s[2*ks + q2][1]));
                pf[2*q2 + 1] = pack_h2(__float2half_rn(s[2*ks + q2][2]), __float2half_rn(s[2*ks + q2][3]));
            }
            uint32_t Vf[8][2];
            #pragma unroll
            for (int np = 0; np < 4; np++) {
                uint32_t a = stb + FARR + (ks * 16 + vr) * LDK + np * 32 + vcb;
                uint32_t t4[4];
                ldsm_x4_t(t4, a);
                Vf[2*np][0] = t4[0]; Vf[2*np][1] = t4[1];
                Vf[2*np+1][0] = t4[2]; Vf[2*np+1][1] = t4[3];
            }
            #pragma unroll
            for (int nt = 0; nt < 8; nt++)
                mma16816(acc_o[nt], pf, Vf[nt]);
        }
        __syncthreads();
    }

    float inv0 = 1.0f / l2[0], inv1 = 1.0f / l2[1];
    int g = lane >> 2;
    int bb = bh >> 4, hh = bh & 15;
    int r_lo = q0 + w * 16 + g, r_hi = r_lo + 8;
    int cbase = hh * 64 + (lane & 3) * 2;
    #pragma unroll
    for (int nt = 0; nt < 8; nt++) {
        int cc = cbase + nt * 8;
        size_t off_lo = ((size_t)bb * SS + r_lo) * DD + cc;
        size_t off_hi = ((size_t)bb * SS + r_hi) * DD + cc;
        *(__half2*)(O_ + off_lo) = __halves2half2(
            __float2half_rn(acc_o[nt][0] * inv0), __float2half_rn(acc_o[nt][1] * inv0));
        *(__half2*)(O_ + off_hi) = __halves2half2(
            __float2half_rn(acc_o[nt][2] * inv1), __float2half_rn(acc_o[nt][3] * inv1));
    }
}

// ---------------- launch ----------------
extern "C" void kernel_launch(void* const* d_in, const int* in_sizes, int n_in,
                              void* d_out, int out_size)
{
    const float* x    = (const float*)d_in[0];
    const float* wq   = (const float*)d_in[1];
    const float* bq   = (const float*)d_in[2];
    const float* wk   = (const float*)d_in[3];
    const float* bk   = (const float*)d_in[4];
    const float* wv   = (const float*)d_in[5];
    const float* bv   = (const float*)d_in[6];
    const float* wo   = (const float*)d_in[7];
    const float* bo   = (const float*)d_in[8];
    const float* g1   = (const float*)d_in[9];
    const float* b1   = (const float*)d_in[10];
    const float* g2   = (const float*)d_in[11];
    const float* b2   = (const float*)d_in[12];
    const float* wfc1 = (const float*)d_in[13];
    const float* bfc1 = (const float*)d_in[14];
    const float* wfc2 = (const float*)d_in[15];
    const float* bfc2 = (const float*)d_in[16];
    float* out = (float*)d_out;

    float *o1;
    cudaGetSymbolAddress((void**)&o1, g_o1);
    __half *xa, *mid, *q, *k, *v;
    cudaGetSymbolAddress((void**)&xa,  g_x);
    cudaGetSymbolAddress((void**)&mid, g_mid);
    cudaGetSymbolAddress((void**)&q,   g_q);
    cudaGetSymbolAddress((void**)&k,   g_k);
    cudaGetSymbolAddress((void**)&v,   g_v);
    __half *wqt, *wkt, *wvt, *wot, *w1t, *w2t;
    cudaGetSymbolAddress((void**)&wqt, g_wqt);
    cudaGetSymbolAddress((void**)&wkt, g_wkt);
    cudaGetSymbolAddress((void**)&wvt, g_wvt);
    cudaGetSymbolAddress((void**)&wot, g_wot);
    cudaGetSymbolAddress((void**)&w1t, g_w1t);
    cudaGetSymbolAddress((void**)&w2t, g_w2t);

    const int GEMM_SMEM = 2 * STG_SZ;  // 40960
    cudaFuncSetAttribute(gemm_mma<2>, cudaFuncAttributeMaxDynamicSharedMemorySize, GEMM_SMEM);
    cudaFuncSetAttribute(gemm_mma<3>, cudaFuncAttributeMaxDynamicSharedMemorySize, GEMM_SMEM);
    cudaFuncSetAttribute(gemm_mma<4>, cudaFuncAttributeMaxDynamicSharedMemorySize, GEMM_SMEM);
    cudaFuncSetAttribute(flash_mma, cudaFuncAttributeMaxDynamicSharedMemorySize, FLASH_SMEM);

    dim3 cb(32, 8);
    wconv<<<dim3(DD / 32, DD / 32), cb>>>(wq,   wqt, DD, DD);
    wconv<<<dim3(DD / 32, DD / 32), cb>>>(wk,   wkt, DD, DD);
    wconv<<<dim3(DD / 32, DD / 32), cb>>>(wv,   wvt, DD, DD);
    wconv<<<dim3(DD / 32, DD / 32), cb>>>(wo,   wot, DD, DD);
    wconv<<<dim3(FFN / 32, DD / 32), cb>>>(wfc1, w1t, DD, FFN);
    wconv<<<dim3(DD / 32, FFN / 32), cb>>>(wfc2, w2t, FFN, DD);

    // 1. LN1 -> fp16
    layernorm_f16<<<ROWS, 256>>>(x, g1, b1, xa);

    // 2. QKV projections -> (B,H,S,DH) fp16 (Q pre-scaled by 1/32)
    dim3 gQKV(DD / 128, ROWS / 128);
    gemm_mma<4><<<gQKV, 256, GEMM_SMEM>>>(xa, wqt, bq, nullptr, nullptr, q, ROWS, DD, DD, 1.0f / 32.0f);
    gemm_mma<4><<<gQKV, 256, GEMM_SMEM>>>(xa, wkt, bk, nullptr, nullptr, k, ROWS, DD, DD, 1.0f);
    gemm_mma<4><<<gQKV, 256, GEMM_SMEM>>>(xa, wvt, bv, nullptr, nullptr, v, ROWS, DD, DD, 1.0f);

    // 3. attention -> fp16 (B,S,D) into xa
    flash_mma<<<dim3(SS / 128, BB * HH), 256, FLASH_SMEM>>>(q, k, v, xa);

    // 4. output projection + residual(x) -> o1 fp32
    gemm_mma<2><<<gQKV, 256, GEMM_SMEM>>>(xa, wot, bo, x, o1, nullptr, ROWS, DD, DD, 1.0f);

    // 5. LN2 -> fp16
    layernorm_f16<<<ROWS, 256>>>(o1, g2, b2, xa);

    // 6. FC1 + GELU -> fp16 mid
    dim3 gFC1(FFN / 128, ROWS / 128);
    gemm_mma<3><<<gFC1, 256, GEMM_SMEM>>>(xa, w1t, bfc1, nullptr, nullptr, mid, ROWS, FFN, DD, 1.0f);

    // 7. FC2 + residual(o1) -> out
    dim3 gFC2(DD / 128, ROWS / 128);
    gemm_mma<2><<<gFC2, 256, GEMM_SMEM>>>(mid, w2t, bfc2, o1, out, nullptr, ROWS, DD, FFN, 1.0f);
}

// round 8
// speedup vs baseline: 2.5311x; 1.0859x over previous
#include <cuda_runtime.h>
#include <cuda_fp16.h>
#include <math.h>
#include <stdint.h>

// ---------------- problem constants ----------------
#define BB 4
#define SS 1024
#define DD 1024
#define HH 16
#define DHH 64
#define FFN 4096
#define ROWS (BB*SS)   // 4096

// ---------------- device scratch ----------------
__device__ float  g_o1 [ROWS*DD];
__device__ __half g_x  [ROWS*DD];               // LN out / attn out
__device__ __half g_mid[(size_t)ROWS*FFN];
__device__ __half g_qkv[3 * ROWS * DD];         // q|k|v in (B,H,S,DH)
__device__ float  g_bqkv[3 * DD];               // fused qkv bias
// transposed fp16 weights, layout [N,K] K-major
__device__ __half g_wqkvt[(size_t)3 * DD * DD]; // wq|wk|wv rows
__device__ __half g_wot[DD*DD];
__device__ __half g_w1t[(size_t)DD*FFN];
__device__ __half g_w2t[(size_t)DD*FFN];

// ---------------- small helpers ----------------
__device__ __forceinline__ uint32_t smem_u32(const void* p) {
    uint32_t a;
    asm("{ .reg .u64 t; cvta.to.shared.u64 t, %1; cvt.u32.u64 %0, t; }" : "=r"(a) : "l"(p));
    return a;
}
__device__ __forceinline__ void cp_async16(uint32_t s, const void* g) {
    asm volatile("cp.async.cg.shared.global [%0], [%1], 16;" :: "r"(s), "l"(g));
}
__device__ __forceinline__ void ldsm_x4(uint32_t* r, uint32_t addr) {
    asm volatile("ldmatrix.sync.aligned.m8n8.x4.shared.b16 {%0,%1,%2,%3}, [%4];"
        : "=r"(r[0]), "=r"(r[1]), "=r"(r[2]), "=r"(r[3]) : "r"(addr));
}
__device__ __forceinline__ void ldsm_x4_t(uint32_t* r, uint32_t addr) {
    asm volatile("ldmatrix.sync.aligned.m8n8.x4.trans.shared.b16 {%0,%1,%2,%3}, [%4];"
        : "=r"(r[0]), "=r"(r[1]), "=r"(r[2]), "=r"(r[3]) : "r"(addr));
}
__device__ __forceinline__ void mma16816(float* d, const uint32_t* a, const uint32_t* b) {
    asm volatile("mma.sync.aligned.m16n8k16.row.col.f32.f16.f16.f32 "
        "{%0,%1,%2,%3}, {%4,%5,%6,%7}, {%8,%9}, {%0,%1,%2,%3};"
        : "+f"(d[0]), "+f"(d[1]), "+f"(d[2]), "+f"(d[3])
        : "r"(a[0]), "r"(a[1]), "r"(a[2]), "r"(a[3]), "r"(b[0]), "r"(b[1]));
}
__device__ __forceinline__ uint32_t pack_h2(__half a, __half b) {
    __half2 t = __halves2half2(a, b);
    return *(uint32_t*)&t;
}

// ---------------- mega weight convert: all 6 weights + bias pack, 1 launch ----
// tile = 32x32. Block ranges:
//  [0,1024)       wq  -> g_wqkvt rows [0,1024)
//  [1024,2048)    wk  -> rows [1024,2048)
//  [2048,3072)    wv  -> rows [2048,3072)
//  [3072,4096)    wo  -> g_wot
//  [4096,8192)    wfc1 (K=1024,N=4096) -> g_w1t
//  [8192,12288)   wfc2 (K=4096,N=1024) -> g_w2t
//  12288          bias pack (bq|bk|bv -> g_bqkv)
__global__ void wconv_all(const float* __restrict__ wq, const float* __restrict__ wk,
                          const float* __restrict__ wv, const float* __restrict__ wo,
                          const float* __restrict__ w1, const float* __restrict__ w2,
                          const float* __restrict__ bq, const float* __restrict__ bk,
                          const float* __restrict__ bv)
{
    int bid = blockIdx.x;
    int tx = threadIdx.x, ty = threadIdx.y;   // 32 x 8
    if (bid == 12288) {
        int t = ty * 32 + tx;
        for (int i = t; i < DD; i += 256) {
            g_bqkv[i]          = bq[i];
            g_bqkv[DD + i]     = bk[i];
            g_bqkv[2*DD + i]   = bv[i];
        }
        return;
    }
    const float* W; __half* T; int K, N, tile, rowoff = 0;
    if (bid < 3072)      { int wsel = bid >> 10; W = wsel == 0 ? wq : (wsel == 1 ? wk : wv);
                           T = g_wqkvt; K = DD; N = DD; tile = bid & 1023; rowoff = wsel * DD; }
    else if (bid < 4096) { W = wo; T = g_wot; K = DD;  N = DD;  tile = bid - 3072; }
    else if (bid < 8192) { W = w1; T = g_w1t; K = DD;  N = FFN; tile = bid - 4096; }
    else                 { W = w2; T = g_w2t; K = FFN; N = DD;  tile = bid - 8192; }
    int ntiles_n = N >> 5;
    int k0 = (tile / ntiles_n) << 5;
    int n0 = (tile % ntiles_n) << 5;

    __shared__ float tl[32][33];
    #pragma unroll
    for (int i = 0; i < 4; i++)
        tl[ty + i*8][tx] = W[(size_t)(k0 + ty + i*8) * N + n0 + tx];
    __syncthreads();
    #pragma unroll
    for (int i = 0; i < 4; i++) {
        int n = n0 + ty + i*8;
        int k = k0 + tx;
        T[(size_t)(rowoff + n) * K + k] = __float2half_rn(tl[tx][ty + i*8]);
    }
}

// ---------------- LayerNorm -> fp16 ----------------
__global__ void layernorm_f16(const float* __restrict__ x, const float* __restrict__ g,
                              const float* __restrict__ b, __half* __restrict__ oh)
{
    __shared__ float red0[8], red1[8];
    int row = blockIdx.x, tid = threadIdx.x;
    const float4* xr = (const float4*)(x + (size_t)row * DD);
    float4 v = xr[tid];
    float s  = v.x + v.y + v.z + v.w;
    float s2 = v.x*v.x + v.y*v.y + v.z*v.z + v.w*v.w;
    #pragma unroll
    for (int o = 16; o; o >>= 1) {
        s  += __shfl_xor_sync(0xffffffffu, s,  o);
        s2 += __shfl_xor_sync(0xffffffffu, s2, o);
    }
    if ((tid & 31) == 0) { red0[tid >> 5] = s; red1[tid >> 5] = s2; }
    __syncthreads();
    float S = 0.f, S2 = 0.f;
    #pragma unroll
    for (int i = 0; i < 8; i++) { S += red0[i]; S2 += red1[i]; }
    float mean = S * (1.f / DD);
    float var  = S2 * (1.f / DD) - mean * mean;
    float rstd = rsqrtf(var + 1e-5f);
    float4 gv = ((const float4*)g)[tid];
    float4 bv = ((const float4*)b)[tid];
    float o0 = (v.x - mean) * rstd * gv.x + bv.x;
    float o1 = (v.y - mean) * rstd * gv.y + bv.y;
    float o2 = (v.z - mean) * rstd * gv.z + bv.z;
    float o3 = (v.w - mean) * rstd * gv.w + bv.w;
    size_t base = (size_t)row * DD + tid * 4;
    *(__half2*)(oh + base)     = __halves2half2(__float2half_rn(o0), __float2half_rn(o1));
    *(__half2*)(oh + base + 2) = __halves2half2(__float2half_rn(o2), __float2half_rn(o3));
}

// ---------------- tensor-core GEMM, fp16 1-pass ----------------
// block 128x128, 8 warps, warp tile 32x64, BK=32, double-buffered.
// EPI 2: bias + residual -> fp32 C
// EPI 3: bias + GELU -> fp16 Ch
// EPI 4: bias + scatter to (B,H,S,DH); fused-QKV aware (which = n>>10, q scaled 1/32)
#define LDB 80
#define ARR 10240
#define STG_SZ 20480
template<int EPI>
__global__ void __launch_bounds__(256, 2)
gemm_mma(const __half* __restrict__ A, const __half* __restrict__ W,
         const float* __restrict__ bias, const float* __restrict__ res,
         float* __restrict__ C, __half* __restrict__ Ch,
         int M, int N, int K)
{
    extern __shared__ char smem[];
    const uint32_t sb = smem_u32(smem);
    const int tid = threadIdx.x;
    const int wid = tid >> 5, lane = tid & 31;
    const int wm = wid & 3, wn = wid >> 2;
    const int m0 = blockIdx.y * 128, n0 = blockIdx.x * 128;

    float acc[2][8][4] = {};
    const int NK = K >> 5;

    auto load_stage = [&](int kc, int buf) {
        int k0 = kc << 5;
        uint32_t stb = sb + buf * STG_SZ;
        #pragma unroll
        for (int i = 0; i < 4; i++) {
            int c = tid + i * 256;
            int arr = c >> 9;
            int cc = c & 511;
            int row = cc >> 2, col = cc & 3;
            const __half* gsrc = (arr ? W + (size_t)(n0 + row) * K
                                      : A + (size_t)(m0 + row) * K) + k0 + col * 8;
            cp_async16(stb + arr * ARR + row * LDB + col * 16, gsrc);
        }
        asm volatile("cp.async.commit_group;" ::: "memory");
    };

    load_stage(0, 0);

    for (int kc = 0; kc < NK; kc++) {
        int buf = kc & 1;
        if (kc + 1 < NK) {
            load_stage(kc + 1, buf ^ 1);
            asm volatile("cp.async.wait_group 1;" ::: "memory");
        } else {
            asm volatile("cp.async.wait_group 0;" ::: "memory");
        }
        __syncthreads();

        uint32_t stb = sb + buf * STG_SZ;
        #pragma unroll
        for (int ks = 0; ks < 2; ks++) {
            uint32_t Af[2][4], Bf[8][2];
            int ar = lane & 15, ac = ks * 16 + (lane >> 4) * 8;
            #pragma unroll
            for (int mt = 0; mt < 2; mt++)
                ldsm_x4(Af[mt], stb + (wm * 32 + mt * 16 + ar) * LDB + ac * 2);
            int gq = lane >> 3, l8 = lane & 7;
            int br = (gq >> 1) * 8 + l8, bc = ks * 16 + (gq & 1) * 8;
            #pragma unroll
            for (int p = 0; p < 4; p++) {
                uint32_t a = stb + ARR + (wn * 64 + p * 16 + br) * LDB + bc * 2;
                uint32_t t[4];
                ldsm_x4(t, a);
                Bf[2*p][0] = t[0]; Bf[2*p][1] = t[1];
                Bf[2*p+1][0] = t[2]; Bf[2*p+1][1] = t[3];
            }
            #pragma unroll
            for (int mt = 0; mt < 2; mt++)
                #pragma unroll
                for (int nt = 0; nt < 8; nt++)
                    mma16816(acc[mt][nt], Af[mt], Bf[nt]);
        }
        __syncthreads();
    }

    // ---- epilogue ----
    int rb = m0 + wm * 32 + (lane >> 2);
    int cb = n0 + wn * 64 + (lane & 3) * 2;
    #pragma unroll
    for (int mt = 0; mt < 2; mt++) {
        #pragma unroll
        for (int half = 0; half < 2; half++) {
            int r = rb + mt * 16 + half * 8;
            #pragma unroll
            for (int nt = 0; nt < 8; nt++) {
                int n = cb + nt * 8;
                float2 bv = *(const float2*)(bias + n);
                float v0 = acc[mt][nt][half * 2 + 0] + bv.x;
                float v1 = acc[mt][nt][half * 2 + 1] + bv.y;
                if (EPI == 2) {
                    float2 rv = *(const float2*)(res + (size_t)r * N + n);
                    v0 += rv.x; v1 += rv.y;
                    *(float2*)(C + (size_t)r * N + n) = make_float2(v0, v1);
                } else if (EPI == 3) {
                    v0 = 0.5f * v0 * (1.0f + erff(v0 * 0.70710678118654752f));
                    v1 = 0.5f * v1 * (1.0f + erff(v1 * 0.70710678118654752f));
                    *(__half2*)(Ch + (size_t)r * N + n) =
                        __halves2half2(__float2half_rn(v0), __float2half_rn(v1));
                } else if (EPI == 4) {
                    int which = n >> 10, n2 = n & 1023;
                    float scl = (which == 0) ? (1.0f / 32.0f) : 1.0f;
                    v0 *= scl; v1 *= scl;
                    int b_ = r >> 10, s = r & 1023, hh = n2 >> 6, dh = n2 & 63;
                    size_t off = (size_t)which * (ROWS * DD)
                               + ((size_t)(b_ * HH + hh) * SS + s) * DHH + dh;
                    *(__half2*)(Ch + off) =
                        __halves2half2(__float2half_rn(v0), __float2half_rn(v1));
                }
            }
        }
    }
}

// ---------------- Flash attention via mma.sync, fp16, 1-pass --------------
#define LDK 144
#define FQ_SZ 18432
#define FST0  18432
#define FARR  9216
#define FST_SZ 18432
#define FLASH_SMEM (FST0 + 2*FST_SZ)   // 55296
__global__ void __launch_bounds__(256)
flash_mma(const __half* __restrict__ Q_, const __half* __restrict__ K_,
          const __half* __restrict__ V_, __half* __restrict__ O_)
{
    extern __shared__ char smc[];
    const uint32_t sb = smem_u32(smc);
    int tid = threadIdx.x, lane = tid & 31, w = tid >> 5;
    int bh = blockIdx.y, q0 = blockIdx.x * 128;
    size_t qbase = ((size_t)bh * SS + q0) * DHH;
    size_t kvbase = (size_t)bh * SS * DHH;

    #pragma unroll
    for (int i = 0; i < 4; i++) {
        int c = tid + i * 256;
        int row = c >> 3, col = c & 7;
        cp_async16(sb + row * LDK + col * 16, Q_ + qbase + row * 64 + col * 8);
    }
    auto load_stage = [&](int t, int buf) {
        size_t base = kvbase + (size_t)t * 64 * DHH;
        #pragma unroll
        for (int i = 0; i < 4; i++) {
            int c = tid + i * 256;
            int arr = c >> 9, cc = c & 511;
            int row = cc >> 3, col = cc & 7;
            const __half* src = (arr ? V_ : K_) + base + row * 64 + col * 8;
            cp_async16(sb + FST0 + buf * FST_SZ + arr * FARR + row * LDK + col * 16, src);
        }
    };
    load_stage(0, 0);
    asm volatile("cp.async.commit_group;" ::: "memory");

    uint32_t qf[4][4];
    float m2[2] = {-1e30f, -1e30f}, l2[2] = {0.f, 0.f};
    float acc_o[8][4] = {};

    for (int t = 0; t < SS / 64; t++) {
        int buf = t & 1;
        if (t + 1 < SS / 64) {
            load_stage(t + 1, (t + 1) & 1);
            asm volatile("cp.async.commit_group;" ::: "memory");
            asm volatile("cp.async.wait_group 1;" ::: "memory");
        } else {
            asm volatile("cp.async.wait_group 0;" ::: "memory");
        }
        __syncthreads();
        if (t == 0) {
            #pragma unroll
            for (int ks = 0; ks < 4; ks++)
                ldsm_x4(qf[ks], sb + (w * 16 + (lane & 15)) * LDK + ks * 32 + (lane >> 4) * 16);
        }
        uint32_t stb = sb + FST0 + buf * FST_SZ;

        float s[8][4] = {};
        int gq = lane >> 3, l8 = lane & 7;
        int br = (gq >> 1) * 8 + l8;
        #pragma unroll
        for (int ks = 0; ks < 4; ks++) {
            uint32_t Bf[8][2];
            int bcB = ks * 32 + (gq & 1) * 16;
            #pragma unroll
            for (int p = 0; p < 4; p++) {
                uint32_t a = stb + (p * 16 + br) * LDK + bcB;
                uint32_t t4[4];
                ldsm_x4(t4, a);
                Bf[2*p][0] = t4[0]; Bf[2*p][1] = t4[1];
                Bf[2*p+1][0] = t4[2]; Bf[2*p+1][1] = t4[3];
            }
            #pragma unroll
            for (int nt = 0; nt < 8; nt++)
                mma16816(s[nt], qf[ks], Bf[nt]);
        }

        float rm0 = -1e30f, rm1 = -1e30f;
        #pragma unroll
        for (int nt = 0; nt < 8; nt++) {
            rm0 = fmaxf(rm0, fmaxf(s[nt][0], s[nt][1]));
            rm1 = fmaxf(rm1, fmaxf(s[nt][2], s[nt][3]));
        }
        rm0 = fmaxf(rm0, __shfl_xor_sync(0xffffffffu, rm0, 1));
        rm0 = fmaxf(rm0, __shfl_xor_sync(0xffffffffu, rm0, 2));
        rm1 = fmaxf(rm1, __shfl_xor_sync(0xffffffffu, rm1, 1));
        rm1 = fmaxf(rm1, __shfl_xor_sync(0xffffffffu, rm1, 2));
        float mn0 = fmaxf(m2[0], rm0), mn1 = fmaxf(m2[1], rm1);
        float al0 = __expf(m2[0] - mn0), al1 = __expf(m2[1] - mn1);
        float rs0 = 0.f, rs1 = 0.f;
        #pragma unroll
        for (int nt = 0; nt < 8; nt++) {
            s[nt][0] = __expf(s[nt][0] - mn0);
            s[nt][1] = __expf(s[nt][1] - mn0);
            s[nt][2] = __expf(s[nt][2] - mn1);
            s[nt][3] = __expf(s[nt][3] - mn1);
            rs0 += s[nt][0] + s[nt][1];
            rs1 += s[nt][2] + s[nt][3];
        }
        rs0 += __shfl_xor_sync(0xffffffffu, rs0, 1);
        rs0 += __shfl_xor_sync(0xffffffffu, rs0, 2);
        rs1 += __shfl_xor_sync(0xffffffffu, rs1, 1);
        rs1 += __shfl_xor_sync(0xffffffffu, rs1, 2);
        l2[0] = l2[0] * al0 + rs0;
        l2[1] = l2[1] * al1 + rs1;
        m2[0] = mn0; m2[1] = mn1;
        #pragma unroll
        for (int nt = 0; nt < 8; nt++) {
            acc_o[nt][0] *= al0; acc_o[nt][1] *= al0;
            acc_o[nt][2] *= al1; acc_o[nt][3] *= al1;
        }

        int vr = ((lane >> 3) & 1) * 8 + (lane & 7);
        int vcb = ((lane >> 4) * 8) * 2;
        #pragma unroll
        for (int ks = 0; ks < 4; ks++) {
            uint32_t pf[4];
            #pragma unroll
            for (int q2 = 0; q2 < 2; q2++) {
                pf[2*q2]     = pack_h2(__float2half_rn(s[2*ks + q2][0]), __float2half_rn(s[2*ks + q2][1]));
                pf[2*q2 + 1] = pack_h2(__float2half_rn(s[2*ks + q2][2]), __float2half_rn(s[2*ks + q2][3]));
            }
            uint32_t Vf[8][2];
            #pragma unroll
            for (int np = 0; np < 4; np++) {
                uint32_t a = stb + FARR + (ks * 16 + vr) * LDK + np * 32 + vcb;
                uint32_t t4[4];
                ldsm_x4_t(t4, a);
                Vf[2*np][0] = t4[0]; Vf[2*np][1] = t4[1];
                Vf[2*np+1][0] = t4[2]; Vf[2*np+1][1] = t4[3];
            }
            #pragma unroll
            for (int nt = 0; nt < 8; nt++)
                mma16816(acc_o[nt], pf, Vf[nt]);
        }
        __syncthreads();
    }

    float inv0 = 1.0f / l2[0], inv1 = 1.0f / l2[1];
    int g = lane >> 2;
    int bb = bh >> 4, hh = bh & 15;
    int r_lo = q0 + w * 16 + g, r_hi = r_lo + 8;
    int cbase = hh * 64 + (lane & 3) * 2;
    #pragma unroll
    for (int nt = 0; nt < 8; nt++) {
        int cc = cbase + nt * 8;
        size_t off_lo = ((size_t)bb * SS + r_lo) * DD + cc;
        size_t off_hi = ((size_t)bb * SS + r_hi) * DD + cc;
        *(__half2*)(O_ + off_lo) = __halves2half2(
            __float2half_rn(acc_o[nt][0] * inv0), __float2half_rn(acc_o[nt][1] * inv0));
        *(__half2*)(O_ + off_hi) = __halves2half2(
            __float2half_rn(acc_o[nt][2] * inv1), __float2half_rn(acc_o[nt][3] * inv1));
    }
}

// ---------------- launch ----------------
extern "C" void kernel_launch(void* const* d_in, const int* in_sizes, int n_in,
                              void* d_out, int out_size)
{
    const float* x    = (const float*)d_in[0];
    const float* wq   = (const float*)d_in[1];
    const float* bq   = (const float*)d_in[2];
    const float* wk   = (const float*)d_in[3];
    const float* bk   = (const float*)d_in[4];
    const float* wv   = (const float*)d_in[5];
    const float* bv   = (const float*)d_in[6];
    const float* wo   = (const float*)d_in[7];
    const float* bo   = (const float*)d_in[8];
    const float* g1   = (const float*)d_in[9];
    const float* b1   = (const float*)d_in[10];
    const float* g2   = (const float*)d_in[11];
    const float* b2   = (const float*)d_in[12];
    const float* wfc1 = (const float*)d_in[13];
    const float* bfc1 = (const float*)d_in[14];
    const float* wfc2 = (const float*)d_in[15];
    const float* bfc2 = (const float*)d_in[16];
    float* out = (float*)d_out;

    float *o1, *bqkv;
    cudaGetSymbolAddress((void**)&o1,   g_o1);
    cudaGetSymbolAddress((void**)&bqkv, g_bqkv);
    __half *xa, *mid, *qkv;
    cudaGetSymbolAddress((void**)&xa,  g_x);
    cudaGetSymbolAddress((void**)&mid, g_mid);
    cudaGetSymbolAddress((void**)&qkv, g_qkv);
    __half *wqkvt, *wot, *w1t, *w2t;
    cudaGetSymbolAddress((void**)&wqkvt, g_wqkvt);
    cudaGetSymbolAddress((void**)&wot,   g_wot);
    cudaGetSymbolAddress((void**)&w1t,   g_w1t);
    cudaGetSymbolAddress((void**)&w2t,   g_w2t);

    const int GEMM_SMEM = 2 * STG_SZ;  // 40960
    cudaFuncSetAttribute(gemm_mma<2>, cudaFuncAttributeMaxDynamicSharedMemorySize, GEMM_SMEM);
    cudaFuncSetAttribute(gemm_mma<3>, cudaFuncAttributeMaxDynamicSharedMemorySize, GEMM_SMEM);
    cudaFuncSetAttribute(gemm_mma<4>, cudaFuncAttributeMaxDynamicSharedMemorySize, GEMM_SMEM);
    cudaFuncSetAttribute(flash_mma, cudaFuncAttributeMaxDynamicSharedMemorySize, FLASH_SMEM);

    // 0. all weight conversions + bias pack, one launch
    wconv_all<<<12289, dim3(32, 8)>>>(wq, wk, wv, wo, wfc1, wfc2, bq, bk, bv);

    // 1. LN1 -> fp16
    layernorm_f16<<<ROWS, 256>>>(x, g1, b1, xa);

    // 2. fused QKV projection -> (3,B,H,S,DH) fp16
    gemm_mma<4><<<dim3(3 * DD / 128, ROWS / 128), 256, GEMM_SMEM>>>(
        xa, wqkvt, bqkv, nullptr, nullptr, qkv, ROWS, 3 * DD, DD);

    // 3. attention -> fp16 (B,S,D) into xa
    flash_mma<<<dim3(SS / 128, BB * HH), 256, FLASH_SMEM>>>(
        qkv, qkv + ROWS * DD, qkv + 2 * ROWS * DD, xa);

    // 4. output projection + residual(x) -> o1 fp32
    gemm_mma<2><<<dim3(DD / 128, ROWS / 128), 256, GEMM_SMEM>>>(
        xa, wot, bo, x, o1, nullptr, ROWS, DD, DD);

    // 5. LN2 -> fp16
    layernorm_f16<<<ROWS, 256>>>(o1, g2, b2, xa);

    // 6. FC1 + GELU -> fp16 mid
    gemm_mma<3><<<dim3(FFN / 128, ROWS / 128), 256, GEMM_SMEM>>>(
        xa, w1t, bfc1, nullptr, nullptr, mid, ROWS, FFN, DD);

    // 7. FC2 + residual(o1) -> out
    gemm_mma<2><<<dim3(DD / 128, ROWS / 128), 256, GEMM_SMEM>>>(
        mid, w2t, bfc2, o1, out, nullptr, ROWS, DD, FFN);
}

// round 10
// speedup vs baseline: 2.6967x; 1.0654x over previous
#include <cuda_runtime.h>
#include <cuda_fp16.h>
#include <math.h>
#include <stdint.h>

// ---------------- problem constants ----------------
#define BB 4
#define SS 1024
#define DD 1024
#define HH 16
#define DHH 64
#define FFN 4096
#define ROWS (BB*SS)   // 4096

// ---------------- device scratch ----------------
__device__ float  g_o1 [ROWS*DD];
__device__ __half g_x  [ROWS*DD];               // LN out / attn out
__device__ __half g_mid[(size_t)ROWS*FFN];
__device__ __half g_qkv[3 * ROWS * DD];         // q|k|v in (B,H,S,DH)
__device__ float  g_bqkv[3 * DD];               // fused qkv bias
// transposed fp16 weights, layout [N,K] K-major
__device__ __half g_wqkvt[(size_t)3 * DD * DD]; // wq|wk|wv rows
__device__ __half g_wot[DD*DD];
__device__ __half g_w1t[(size_t)DD*FFN];
__device__ __half g_w2t[(size_t)DD*FFN];

// ---------------- small helpers ----------------
__device__ __forceinline__ uint32_t smem_u32(const void* p) {
    uint32_t a;
    asm("{ .reg .u64 t; cvta.to.shared.u64 t, %1; cvt.u32.u64 %0, t; }" : "=r"(a) : "l"(p));
    return a;
}
__device__ __forceinline__ void cp_async16(uint32_t s, const void* g) {
    asm volatile("cp.async.cg.shared.global [%0], [%1], 16;" :: "r"(s), "l"(g));
}
__device__ __forceinline__ void ldsm_x4(uint32_t* r, uint32_t addr) {
    asm volatile("ldmatrix.sync.aligned.m8n8.x4.shared.b16 {%0,%1,%2,%3}, [%4];"
        : "=r"(r[0]), "=r"(r[1]), "=r"(r[2]), "=r"(r[3]) : "r"(addr));
}
__device__ __forceinline__ void ldsm_x4_t(uint32_t* r, uint32_t addr) {
    asm volatile("ldmatrix.sync.aligned.m8n8.x4.trans.shared.b16 {%0,%1,%2,%3}, [%4];"
        : "=r"(r[0]), "=r"(r[1]), "=r"(r[2]), "=r"(r[3]) : "r"(addr));
}
__device__ __forceinline__ void mma16816(float* d, const uint32_t* a, const uint32_t* b) {
    asm volatile("mma.sync.aligned.m16n8k16.row.col.f32.f16.f16.f32 "
        "{%0,%1,%2,%3}, {%4,%5,%6,%7}, {%8,%9}, {%0,%1,%2,%3};"
        : "+f"(d[0]), "+f"(d[1]), "+f"(d[2]), "+f"(d[3])
        : "r"(a[0]), "r"(a[1]), "r"(a[2]), "r"(a[3]), "r"(b[0]), "r"(b[1]));
}
__device__ __forceinline__ uint32_t pack_h2(__half a, __half b) {
    __half2 t = __halves2half2(a, b);
    return *(uint32_t*)&t;
}

// ---------------- mega kernel: weight conversions + bias pack + LN1 -------
// Block ranges:
//  [0,3072)      wq|wk|wv -> g_wqkvt
//  [3072,4096)   wo -> g_wot
//  [4096,8192)   wfc1 -> g_w1t
//  [8192,12288)  wfc2 -> g_w2t
//  12288         bias pack
//  [12289,16385) LN1 row (bid-12289)
__global__ void wconv_all(const float* __restrict__ wq, const float* __restrict__ wk,
                          const float* __restrict__ wv, const float* __restrict__ wo,
                          const float* __restrict__ w1, const float* __restrict__ w2,
                          const float* __restrict__ bq, const float* __restrict__ bk,
                          const float* __restrict__ bv,
                          const float* __restrict__ x, const float* __restrict__ g1,
                          const float* __restrict__ b1, __half* __restrict__ xa)
{
    int bid = blockIdx.x;
    int tx = threadIdx.x, ty = threadIdx.y;   // 32 x 8
    int t = ty * 32 + tx;
    __shared__ float tl[32][33];
    __shared__ float red0[8], red1[8];

    if (bid >= 12289) {
        // ---- LN1 for row (bid-12289) ----
        int row = bid - 12289;
        const float4* xr = (const float4*)(x + (size_t)row * DD);
        float4 v = xr[t];
        float s  = v.x + v.y + v.z + v.w;
        float s2 = v.x*v.x + v.y*v.y + v.z*v.z + v.w*v.w;
        #pragma unroll
        for (int o = 16; o; o >>= 1) {
            s  += __shfl_xor_sync(0xffffffffu, s,  o);
            s2 += __shfl_xor_sync(0xffffffffu, s2, o);
        }
        if ((t & 31) == 0) { red0[t >> 5] = s; red1[t >> 5] = s2; }
        __syncthreads();
        float S = 0.f, S2 = 0.f;
        #pragma unroll
        for (int i = 0; i < 8; i++) { S += red0[i]; S2 += red1[i]; }
        float mean = S * (1.f / DD);
        float var  = S2 * (1.f / DD) - mean * mean;
        float rstd = rsqrtf(var + 1e-5f);
        float4 gv = ((const float4*)g1)[t];
        float4 bv4 = ((const float4*)b1)[t];
        float o0 = (v.x - mean) * rstd * gv.x + bv4.x;
        float o1 = (v.y - mean) * rstd * gv.y + bv4.y;
        float o2 = (v.z - mean) * rstd * gv.z + bv4.z;
        float o3 = (v.w - mean) * rstd * gv.w + bv4.w;
        size_t base = (size_t)row * DD + t * 4;
        *(__half2*)(xa + base)     = __halves2half2(__float2half_rn(o0), __float2half_rn(o1));
        *(__half2*)(xa + base + 2) = __halves2half2(__float2half_rn(o2), __float2half_rn(o3));
        return;
    }
    if (bid == 12288) {
        for (int i = t; i < DD; i += 256) {
            g_bqkv[i]        = bq[i];
            g_bqkv[DD + i]   = bk[i];
            g_bqkv[2*DD + i] = bv[i];
        }
        return;
    }
    const float* W; __half* T; int K, N, tile, rowoff = 0;
    if (bid < 3072)      { int wsel = bid >> 10; W = wsel == 0 ? wq : (wsel == 1 ? wk : wv);
                           T = g_wqkvt; K = DD; N = DD; tile = bid & 1023; rowoff = wsel * DD; }
    else if (bid < 4096) { W = wo; T = g_wot; K = DD;  N = DD;  tile = bid - 3072; }
    else if (bid < 8192) { W = w1; T = g_w1t; K = DD;  N = FFN; tile = bid - 4096; }
    else                 { W = w2; T = g_w2t; K = FFN; N = DD;  tile = bid - 8192; }
    int ntiles_n = N >> 5;
    int k0 = (tile / ntiles_n) << 5;
    int n0 = (tile % ntiles_n) << 5;

    #pragma unroll
    for (int i = 0; i < 4; i++)
        tl[ty + i*8][tx] = W[(size_t)(k0 + ty + i*8) * N + n0 + tx];
    __syncthreads();
    #pragma unroll
    for (int i = 0; i < 4; i++) {
        int n = n0 + ty + i*8;
        int k = k0 + tx;
        T[(size_t)(rowoff + n) * K + k] = __float2half_rn(tl[tx][ty + i*8]);
    }
}

// ---------------- LayerNorm -> fp16 (LN2) ----------------
__global__ void layernorm_f16(const float* __restrict__ x, const float* __restrict__ g,
                              const float* __restrict__ b, __half* __restrict__ oh)
{
    __shared__ float red0[8], red1[8];
    int row = blockIdx.x, tid = threadIdx.x;
    const float4* xr = (const float4*)(x + (size_t)row * DD);
    float4 v = xr[tid];
    float s  = v.x + v.y + v.z + v.w;
    float s2 = v.x*v.x + v.y*v.y + v.z*v.z + v.w*v.w;
    #pragma unroll
    for (int o = 16; o; o >>= 1) {
        s  += __shfl_xor_sync(0xffffffffu, s,  o);
        s2 += __shfl_xor_sync(0xffffffffu, s2, o);
    }
    if ((tid & 31) == 0) { red0[tid >> 5] = s; red1[tid >> 5] = s2; }
    __syncthreads();
    float S = 0.f, S2 = 0.f;
    #pragma unroll
    for (int i = 0; i < 8; i++) { S += red0[i]; S2 += red1[i]; }
    float mean = S * (1.f / DD);
    float var  = S2 * (1.f / DD) - mean * mean;
    float rstd = rsqrtf(var + 1e-5f);
    float4 gv = ((const float4*)g)[tid];
    float4 bv = ((const float4*)b)[tid];
    float o0 = (v.x - mean) * rstd * gv.x + bv.x;
    float o1 = (v.y - mean) * rstd * gv.y + bv.y;
    float o2 = (v.z - mean) * rstd * gv.z + bv.z;
    float o3 = (v.w - mean) * rstd * gv.w + bv.w;
    size_t base = (size_t)row * DD + tid * 4;
    *(__half2*)(oh + base)     = __halves2half2(__float2half_rn(o0), __float2half_rn(o1));
    *(__half2*)(oh + base + 2) = __halves2half2(__float2half_rn(o2), __float2half_rn(o3));
}

// ---------------- tensor-core GEMM, fp16 1-pass, 3-stage pipeline ---------
// block 128x128, 8 warps, warp tile 32x64, BK=32.
#define LDB 80
#define ARR 10240
#define STG_SZ 20480
#define GSTAGES 3
template<int EPI>
__global__ void __launch_bounds__(256, 2)
gemm_mma(const __half* __restrict__ A, const __half* __restrict__ W,
         const float* __restrict__ bias, const float* __restrict__ res,
         float* __restrict__ C, __half* __restrict__ Ch,
         int M, int N, int K)
{
    extern __shared__ char smem[];
    const uint32_t sb = smem_u32(smem);
    const int tid = threadIdx.x;
    const int wid = tid >> 5, lane = tid & 31;
    const int wm = wid & 3, wn = wid >> 2;
    const int m0 = blockIdx.y * 128, n0 = blockIdx.x * 128;

    float acc[2][8][4] = {};
    const int NK = K >> 5;

    auto load_stage = [&](int kc, int buf) {
        int k0 = kc << 5;
        uint32_t stb = sb + buf * STG_SZ;
        #pragma unroll
        for (int i = 0; i < 4; i++) {
            int c = tid + i * 256;
            int arr = c >> 9;
            int cc = c & 511;
            int row = cc >> 2, col = cc & 3;
            const __half* gsrc = (arr ? W + (size_t)(n0 + row) * K
                                      : A + (size_t)(m0 + row) * K) + k0 + col * 8;
            cp_async16(stb + arr * ARR + row * LDB + col * 16, gsrc);
        }
    };

    load_stage(0, 0);
    asm volatile("cp.async.commit_group;" ::: "memory");
    load_stage(1, 1);
    asm volatile("cp.async.commit_group;" ::: "memory");

    for (int kc = 0; kc < NK; kc++) {
        if (kc + 2 < NK) load_stage(kc + 2, (kc + 2) % GSTAGES);
        asm volatile("cp.async.commit_group;" ::: "memory");
        asm volatile("cp.async.wait_group 2;" ::: "memory");
        __syncthreads();

        uint32_t stb = sb + (kc % GSTAGES) * STG_SZ;
        #pragma unroll
        for (int ks = 0; ks < 2; ks++) {
            uint32_t Af[2][4], Bf[8][2];
            int ar = lane & 15, ac = ks * 16 + (lane >> 4) * 8;
            #pragma unroll
            for (int mt = 0; mt < 2; mt++)
                ldsm_x4(Af[mt], stb + (wm * 32 + mt * 16 + ar) * LDB + ac * 2);
            int gq = lane >> 3, l8 = lane & 7;
            int br = (gq >> 1) * 8 + l8, bc = ks * 16 + (gq & 1) * 8;
            #pragma unroll
            for (int p = 0; p < 4; p++) {
                uint32_t a = stb + ARR + (wn * 64 + p * 16 + br) * LDB + bc * 2;
                uint32_t t[4];
                ldsm_x4(t, a);
                Bf[2*p][0] = t[0]; Bf[2*p][1] = t[1];
                Bf[2*p+1][0] = t[2]; Bf[2*p+1][1] = t[3];
            }
            #pragma unroll
            for (int mt = 0; mt < 2; mt++)
                #pragma unroll
                for (int nt = 0; nt < 8; nt++)
                    mma16816(acc[mt][nt], Af[mt], Bf[nt]);
        }
        __syncthreads();
    }

    // ---- epilogue ----
    int rb = m0 + wm * 32 + (lane >> 2);
    int cb = n0 + wn * 64 + (lane & 3) * 2;
    #pragma unroll
    for (int mt = 0; mt < 2; mt++) {
        #pragma unroll
        for (int half = 0; half < 2; half++) {
            int r = rb + mt * 16 + half * 8;
            #pragma unroll
            for (int nt = 0; nt < 8; nt++) {
                int n = cb + nt * 8;
                float2 bv = *(const float2*)(bias + n);
                float v0 = acc[mt][nt][half * 2 + 0] + bv.x;
                float v1 = acc[mt][nt][half * 2 + 1] + bv.y;
                if (EPI == 2) {
                    float2 rv = *(const float2*)(res + (size_t)r * N + n);
                    v0 += rv.x; v1 += rv.y;
                    *(float2*)(C + (size_t)r * N + n) = make_float2(v0, v1);
                } else if (EPI == 3) {
                    v0 = 0.5f * v0 * (1.0f + erff(v0 * 0.70710678118654752f));
                    v1 = 0.5f * v1 * (1.0f + erff(v1 * 0.70710678118654752f));
                    *(__half2*)(Ch + (size_t)r * N + n) =
                        __halves2half2(__float2half_rn(v0), __float2half_rn(v1));
                } else if (EPI == 4) {
                    int which = n >> 10, n2 = n & 1023;
                    float scl = (which == 0) ? (1.0f / 32.0f) : 1.0f;
                    v0 *= scl; v1 *= scl;
                    int b_ = r >> 10, s = r & 1023, hh = n2 >> 6, dh = n2 & 63;
                    size_t off = (size_t)which * (ROWS * DD)
                               + ((size_t)(b_ * HH + hh) * SS + s) * DHH + dh;
                    *(__half2*)(Ch + off) =
                        __halves2half2(__float2half_rn(v0), __float2half_rn(v1));
                }
            }
        }
    }
}

// ---------------- Flash attention via mma.sync, fp16, 3-stage KV ----------
#define LDK 144
#define FQ_SZ 18432
#define FST0  18432
#define FARR  9216
#define FST_SZ 18432
#define FSTAGES 3
#define FLASH_SMEM (FST0 + FSTAGES*FST_SZ)   // 73728
__global__ void __launch_bounds__(256, 2)
flash_mma(const __half* __restrict__ Q_, const __half* __restrict__ K_,
          const __half* __restrict__ V_, __half* __restrict__ O_)
{
    extern __shared__ char smc[];
    const uint32_t sb = smem_u32(smc);
    int tid = threadIdx.x, lane = tid & 31, w = tid >> 5;
    int bh = blockIdx.y, q0 = blockIdx.x * 128;
    size_t qbase = ((size_t)bh * SS + q0) * DHH;
    size_t kvbase = (size_t)bh * SS * DHH;
    const int NT = SS / 64;

    #pragma unroll
    for (int i = 0; i < 4; i++) {
        int c = tid + i * 256;
        int row = c >> 3, col = c & 7;
        cp_async16(sb + row * LDK + col * 16, Q_ + qbase + row * 64 + col * 8);
    }
    asm volatile("cp.async.commit_group;" ::: "memory");
    auto load_stage = [&](int t, int buf) {
        size_t base = kvbase + (size_t)t * 64 * DHH;
        #pragma unroll
        for (int i = 0; i < 4; i++) {
            int c = tid + i * 256;
            int arr = c >> 9, cc = c & 511;
            int row = cc >> 3, col = cc & 7;
            const __half* src = (arr ? V_ : K_) + base + row * 64 + col * 8;
            cp_async16(sb + FST0 + buf * FST_SZ + arr * FARR + row * LDK + col * 16, src);
        }
    };
    load_stage(0, 0);
    asm volatile("cp.async.commit_group;" ::: "memory");
    load_stage(1, 1);
    asm volatile("cp.async.commit_group;" ::: "memory");

    uint32_t qf[4][4];
    float m2[2] = {-1e30f, -1e30f}, l2[2] = {0.f, 0.f};
    float acc_o[8][4] = {};

    for (int t = 0; t < NT; t++) {
        if (t + 2 < NT) load_stage(t + 2, (t + 2) % FSTAGES);
        asm volatile("cp.async.commit_group;" ::: "memory");
        asm volatile("cp.async.wait_group 2;" ::: "memory");
        __syncthreads();
        if (t == 0) {
            #pragma unroll
            for (int ks = 0; ks < 4; ks++)
                ldsm_x4(qf[ks], sb + (w * 16 + (lane & 15)) * LDK + ks * 32 + (lane >> 4) * 16);
        }
        uint32_t stb = sb + FST0 + (t % FSTAGES) * FST_SZ;

        float s[8][4] = {};
        int gq = lane >> 3, l8 = lane & 7;
        int br = (gq >> 1) * 8 + l8;
        #pragma unroll
        for (int ks = 0; ks < 4; ks++) {
            uint32_t Bf[8][2];
            int bcB = ks * 32 + (gq & 1) * 16;
            #pragma unroll
            for (int p = 0; p < 4; p++) {
                uint32_t a = stb + (p * 16 + br) * LDK + bcB;
                uint32_t t4[4];
                ldsm_x4(t4, a);
                Bf[2*p][0] = t4[0]; Bf[2*p][1] = t4[1];
                Bf[2*p+1][0] = t4[2]; Bf[2*p+1][1] = t4[3];
            }
            #pragma unroll
            for (int nt = 0; nt < 8; nt++)
                mma16816(s[nt], qf[ks], Bf[nt]);
        }

        float rm0 = -1e30f, rm1 = -1e30f;
        #pragma unroll
        for (int nt = 0; nt < 8; nt++) {
            rm0 = fmaxf(rm0, fmaxf(s[nt][0], s[nt][1]));
            rm1 = fmaxf(rm1, fmaxf(s[nt][2], s[nt][3]));
        }
        rm0 = fmaxf(rm0, __shfl_xor_sync(0xffffffffu, rm0, 1));
        rm0 = fmaxf(rm0, __shfl_xor_sync(0xffffffffu, rm0, 2));
        rm1 = fmaxf(rm1, __shfl_xor_sync(0xffffffffu, rm1, 1));
        rm1 = fmaxf(rm1, __shfl_xor_sync(0xffffffffu, rm1, 2));
        float mn0 = fmaxf(m2[0], rm0), mn1 = fmaxf(m2[1], rm1);
        float al0 = __expf(m2[0] - mn0), al1 = __expf(m2[1] - mn1);
        float rs0 = 0.f, rs1 = 0.f;
        #pragma unroll
        for (int nt = 0; nt < 8; nt++) {
            s[nt][0] = __expf(s[nt][0] - mn0);
            s[nt][1] = __expf(s[nt][1] - mn0);
            s[nt][2] = __expf(s[nt][2] - mn1);
            s[nt][3] = __expf(s[nt][3] - mn1);
            rs0 += s[nt][0] + s[nt][1];
            rs1 += s[nt][2] + s[nt][3];
        }
        rs0 += __shfl_xor_sync(0xffffffffu, rs0, 1);
        rs0 += __shfl_xor_sync(0xffffffffu, rs0, 2);
        rs1 += __shfl_xor_sync(0xffffffffu, rs1, 1);
        rs1 += __shfl_xor_sync(0xffffffffu, rs1, 2);
        l2[0] = l2[0] * al0 + rs0;
        l2[1] = l2[1] * al1 + rs1;
        m2[0] = mn0; m2[1] = mn1;
        #pragma unroll
        for (int nt = 0; nt < 8; nt++) {
            acc_o[nt][0] *= al0; acc_o[nt][1] *= al0;
            acc_o[nt][2] *= al1; acc_o[nt][3] *= al1;
        }

        int vr = ((lane >> 3) & 1) * 8 + (lane & 7);
        int vcb = ((lane >> 4) * 8) * 2;
        #pragma unroll
        for (int ks = 0; ks < 4; ks++) {
            uint32_t pf[4];
            #pragma unroll
            for (int q2 = 0; q2 < 2; q2++) {
                pf[2*q2]     = pack_h2(__float2half_rn(s[2*ks + q2][0]), __float2half_rn(s[2*ks + q2][1]));
                pf[2*q2 + 1] = pack_h2(__float2half_rn(s[2*ks + q2][2]), __float2half_rn(s[2*ks + q2][3]));
            }
            uint32_t Vf[8][2];
            #pragma unroll
            for (int np = 0; np < 4; np++) {
                uint32_t a = stb + FARR + (ks * 16 + vr) * LDK + np * 32 + vcb;
                uint32_t t4[4];
                ldsm_x4_t(t4, a);
                Vf[2*np][0] = t4[0]; Vf[2*np][1] = t4[1];
                Vf[2*np+1][0] = t4[2]; Vf[2*np+1][1] = t4[3];
            }
            #pragma unroll
            for (int nt = 0; nt < 8; nt++)
                mma16816(acc_o[nt], pf, Vf[nt]);
        }
        __syncthreads();
    }

    float inv0 = 1.0f / l2[0], inv1 = 1.0f / l2[1];
    int g = lane >> 2;
    int bb = bh >> 4, hh = bh & 15;
    int r_lo = q0 + w * 16 + g, r_hi = r_lo + 8;
    int cbase = hh * 64 + (lane & 3) * 2;
    #pragma unroll
    for (int nt = 0; nt < 8; nt++) {
        int cc = cbase + nt * 8;
        size_t off_lo = ((size_t)bb * SS + r_lo) * DD + cc;
        size_t off_hi = ((size_t)bb * SS + r_hi) * DD + cc;
        *(__half2*)(O_ + off_lo) = __halves2half2(
            __float2half_rn(acc_o[nt][0] * inv0), __float2half_rn(acc_o[nt][1] * inv0));
        *(__half2*)(O_ + off_hi) = __halves2half2(
            __float2half_rn(acc_o[nt][2] * inv1), __float2half_rn(acc_o[nt][3] * inv1));
    }
}

// ---------------- launch ----------------
extern "C" void kernel_launch(void* const* d_in, const int* in_sizes, int n_in,
                              void* d_out, int out_size)
{
    const float* x    = (const float*)d_in[0];
    const float* wq   = (const float*)d_in[1];
    const float* bq   = (const float*)d_in[2];
    const float* wk   = (const float*)d_in[3];
    const float* bk   = (const float*)d_in[4];
    const float* wv   = (const float*)d_in[5];
    const float* bv   = (const float*)d_in[6];
    const float* wo   = (const float*)d_in[7];
    const float* bo   = (const float*)d_in[8];
    const float* g1   = (const float*)d_in[9];
    const float* b1   = (const float*)d_in[10];
    const float* g2   = (const float*)d_in[11];
    const float* b2   = (const float*)d_in[12];
    const float* wfc1 = (const float*)d_in[13];
    const float* bfc1 = (const float*)d_in[14];
    const float* wfc2 = (const float*)d_in[15];
    const float* bfc2 = (const float*)d_in[16];
    float* out = (float*)d_out;

    float *o1, *bqkv;
    cudaGetSymbolAddress((void**)&o1,   g_o1);
    cudaGetSymbolAddress((void**)&bqkv, g_bqkv);
    __half *xa, *mid, *qkv;
    cudaGetSymbolAddress((void**)&xa,  g_x);
    cudaGetSymbolAddress((void**)&mid, g_mid);
    cudaGetSymbolAddress((void**)&qkv, g_qkv);
    __half *wqkvt, *wot, *w1t, *w2t;
    cudaGetSymbolAddress((void**)&wqkvt, g_wqkvt);
    cudaGetSymbolAddress((void**)&wot,   g_wot);
    cudaGetSymbolAddress((void**)&w1t,   g_w1t);
    cudaGetSymbolAddress((void**)&w2t,   g_w2t);

    const int GEMM_SMEM = GSTAGES * STG_SZ;  // 61440
    cudaFuncSetAttribute(gemm_mma<2>, cudaFuncAttributeMaxDynamicSharedMemorySize, GEMM_SMEM);
    cudaFuncSetAttribute(gemm_mma<3>, cudaFuncAttributeMaxDynamicSharedMemorySize, GEMM_SMEM);
    cudaFuncSetAttribute(gemm_mma<4>, cudaFuncAttributeMaxDynamicSharedMemorySize, GEMM_SMEM);
    cudaFuncSetAttribute(flash_mma, cudaFuncAttributeMaxDynamicSharedMemorySize, FLASH_SMEM);

    // 0. weights + bias pack + LN1, one launch
    wconv_all<<<16385, dim3(32, 8)>>>(wq, wk, wv, wo, wfc1, wfc2, bq, bk, bv,
                                      x, g1, b1, xa);

    // 1. fused QKV projection -> (3,B,H,S,DH) fp16
    gemm_mma<4><<<dim3(3 * DD / 128, ROWS / 128), 256, GEMM_SMEM>>>(
        xa, wqkvt, bqkv, nullptr, nullptr, qkv, ROWS, 3 * DD, DD);

    // 2. attention -> fp16 (B,S,D) into xa
    flash_mma<<<dim3(SS / 128, BB * HH), 256, FLASH_SMEM>>>(
        qkv, qkv + ROWS * DD, qkv + 2 * ROWS * DD, xa);

    // 3. output projection + residual(x) -> o1 fp32
    gemm_mma<2><<<dim3(DD / 128, ROWS / 128), 256, GEMM_SMEM>>>(
        xa, wot, bo, x, o1, nullptr, ROWS, DD, DD);

    // 4. LN2 -> fp16
    layernorm_f16<<<ROWS, 256>>>(o1, g2, b2, xa);

    // 5. FC1 + GELU -> fp16 mid
    gemm_mma<3><<<dim3(FFN / 128, ROWS / 128), 256, GEMM_SMEM>>>(
        xa, w1t, bfc1, nullptr, nullptr, mid, ROWS, FFN, DD);

    // 6. FC2 + residual(o1) -> out
    gemm_mma<2><<<dim3(DD / 128, ROWS / 128), 256, GEMM_SMEM>>>(
        mid, w2t, bfc2, o1, out, nullptr, ROWS, DD, FFN);
}

// round 11
// speedup vs baseline: 2.8475x; 1.0559x over previous
#include <cuda_runtime.h>
#include <cuda_fp16.h>
#include <math.h>
#include <stdint.h>

// ---------------- problem constants ----------------
#define BB 4
#define SS 1024
#define DD 1024
#define HH 16
#define DHH 64
#define FFN 4096
#define ROWS (BB*SS)   // 4096

// ---------------- device scratch ----------------
__device__ float  g_o1 [ROWS*DD];
__device__ __half g_x  [ROWS*DD];               // LN out / attn out
__device__ __half g_mid[(size_t)ROWS*FFN];
__device__ __half g_qkv[3 * ROWS * DD];         // q|k|v in (B,H,S,DH)
__device__ float  g_bqkv[3 * DD];               // fused qkv bias
// transposed fp16 weights, layout [N,K] K-major
__device__ __half g_wqkvt[(size_t)3 * DD * DD]; // wq|wk|wv rows
__device__ __half g_wot[DD*DD];
__device__ __half g_w1t[(size_t)DD*FFN];
__device__ __half g_w2t[(size_t)DD*FFN];

// ---------------- small helpers ----------------
__device__ __forceinline__ uint32_t smem_u32(const void* p) {
    uint32_t a;
    asm("{ .reg .u64 t; cvta.to.shared.u64 t, %1; cvt.u32.u64 %0, t; }" : "=r"(a) : "l"(p));
    return a;
}
__device__ __forceinline__ void cp_async16(uint32_t s, const void* g) {
    asm volatile("cp.async.cg.shared.global [%0], [%1], 16;" :: "r"(s), "l"(g));
}
__device__ __forceinline__ void ldsm_x4(uint32_t* r, uint32_t addr) {
    asm volatile("ldmatrix.sync.aligned.m8n8.x4.shared.b16 {%0,%1,%2,%3}, [%4];"
        : "=r"(r[0]), "=r"(r[1]), "=r"(r[2]), "=r"(r[3]) : "r"(addr));
}
__device__ __forceinline__ void ldsm_x4_t(uint32_t* r, uint32_t addr) {
    asm volatile("ldmatrix.sync.aligned.m8n8.x4.trans.shared.b16 {%0,%1,%2,%3}, [%4];"
        : "=r"(r[0]), "=r"(r[1]), "=r"(r[2]), "=r"(r[3]) : "r"(addr));
}
__device__ __forceinline__ void mma16816(float* d, const uint32_t* a, const uint32_t* b) {
    asm volatile("mma.sync.aligned.m16n8k16.row.col.f32.f16.f16.f32 "
        "{%0,%1,%2,%3}, {%4,%5,%6,%7}, {%8,%9}, {%0,%1,%2,%3};"
        : "+f"(d[0]), "+f"(d[1]), "+f"(d[2]), "+f"(d[3])
        : "r"(a[0]), "r"(a[1]), "r"(a[2]), "r"(a[3]), "r"(b[0]), "r"(b[1]));
}
__device__ __forceinline__ uint32_t pack_h2(__half a, __half b) {
    __half2 t = __halves2half2(a, b);
    return *(uint32_t*)&t;
}

// ---------------- mega kernel: weight conversions + bias pack + LN1 -------
__global__ void wconv_all(const float* __restrict__ wq, const float* __restrict__ wk,
                          const float* __restrict__ wv, const float* __restrict__ wo,
                          const float* __restrict__ w1, const float* __restrict__ w2,
                          const float* __restrict__ bq, const float* __restrict__ bk,
                          const float* __restrict__ bv,
                          const float* __restrict__ x, const float* __restrict__ g1,
                          const float* __restrict__ b1, __half* __restrict__ xa)
{
    int bid = blockIdx.x;
    int tx = threadIdx.x, ty = threadIdx.y;   // 32 x 8
    int t = ty * 32 + tx;
    __shared__ float tl[32][33];
    __shared__ float red0[8], red1[8];

    if (bid >= 12289) {
        int row = bid - 12289;
        const float4* xr = (const float4*)(x + (size_t)row * DD);
        float4 v = xr[t];
        float s  = v.x + v.y + v.z + v.w;
        float s2 = v.x*v.x + v.y*v.y + v.z*v.z + v.w*v.w;
        #pragma unroll
        for (int o = 16; o; o >>= 1) {
            s  += __shfl_xor_sync(0xffffffffu, s,  o);
            s2 += __shfl_xor_sync(0xffffffffu, s2, o);
        }
        if ((t & 31) == 0) { red0[t >> 5] = s; red1[t >> 5] = s2; }
        __syncthreads();
        float S = 0.f, S2 = 0.f;
        #pragma unroll
        for (int i = 0; i < 8; i++) { S += red0[i]; S2 += red1[i]; }
        float mean = S * (1.f / DD);
        float var  = S2 * (1.f / DD) - mean * mean;
        float rstd = rsqrtf(var + 1e-5f);
        float4 gv = ((const float4*)g1)[t];
        float4 bv4 = ((const float4*)b1)[t];
        float o0 = (v.x - mean) * rstd * gv.x + bv4.x;
        float o1 = (v.y - mean) * rstd * gv.y + bv4.y;
        float o2 = (v.z - mean) * rstd * gv.z + bv4.z;
        float o3 = (v.w - mean) * rstd * gv.w + bv4.w;
        size_t base = (size_t)row * DD + t * 4;
        *(__half2*)(xa + base)     = __halves2half2(__float2half_rn(o0), __float2half_rn(o1));
        *(__half2*)(xa + base + 2) = __halves2half2(__float2half_rn(o2), __float2half_rn(o3));
        return;
    }
    if (bid == 12288) {
        for (int i = t; i < DD; i += 256) {
            g_bqkv[i]        = bq[i];
            g_bqkv[DD + i]   = bk[i];
            g_bqkv[2*DD + i] = bv[i];
        }
        return;
    }
    const float* W; __half* T; int K, N, tile, rowoff = 0;
    if (bid < 3072)      { int wsel = bid >> 10; W = wsel == 0 ? wq : (wsel == 1 ? wk : wv);
                           T = g_wqkvt; K = DD; N = DD; tile = bid & 1023; rowoff = wsel * DD; }
    else if (bid < 4096) { W = wo; T = g_wot; K = DD;  N = DD;  tile = bid - 3072; }
    else if (bid < 8192) { W = w1; T = g_w1t; K = DD;  N = FFN; tile = bid - 4096; }
    else                 { W = w2; T = g_w2t; K = FFN; N = DD;  tile = bid - 8192; }
    int ntiles_n = N >> 5;
    int k0 = (tile / ntiles_n) << 5;
    int n0 = (tile % ntiles_n) << 5;

    #pragma unroll
    for (int i = 0; i < 4; i++)
        tl[ty + i*8][tx] = W[(size_t)(k0 + ty + i*8) * N + n0 + tx];
    __syncthreads();
    #pragma unroll
    for (int i = 0; i < 4; i++) {
        int n = n0 + ty + i*8;
        int k = k0 + tx;
        T[(size_t)(rowoff + n) * K + k] = __float2half_rn(tl[tx][ty + i*8]);
    }
}

// ---------------- LayerNorm -> fp16 (LN2) ----------------
__global__ void layernorm_f16(const float* __restrict__ x, const float* __restrict__ g,
                              const float* __restrict__ b, __half* __restrict__ oh)
{
    __shared__ float red0[8], red1[8];
    int row = blockIdx.x, tid = threadIdx.x;
    const float4* xr = (const float4*)(x + (size_t)row * DD);
    float4 v = xr[tid];
    float s  = v.x + v.y + v.z + v.w;
    float s2 = v.x*v.x + v.y*v.y + v.z*v.z + v.w*v.w;
    #pragma unroll
    for (int o = 16; o; o >>= 1) {
        s  += __shfl_xor_sync(0xffffffffu, s,  o);
        s2 += __shfl_xor_sync(0xffffffffu, s2, o);
    }
    if ((tid & 31) == 0) { red0[tid >> 5] = s; red1[tid >> 5] = s2; }
    __syncthreads();
    float S = 0.f, S2 = 0.f;
    #pragma unroll
    for (int i = 0; i < 8; i++) { S += red0[i]; S2 += red1[i]; }
    float mean = S * (1.f / DD);
    float var  = S2 * (1.f / DD) - mean * mean;
    float rstd = rsqrtf(var + 1e-5f);
    float4 gv = ((const float4*)g)[tid];
    float4 bv = ((const float4*)b)[tid];
    float o0 = (v.x - mean) * rstd * gv.x + bv.x;
    float o1 = (v.y - mean) * rstd * gv.y + bv.y;
    float o2 = (v.z - mean) * rstd * gv.z + bv.z;
    float o3 = (v.w - mean) * rstd * gv.w + bv.w;
    size_t base = (size_t)row * DD + tid * 4;
    *(__half2*)(oh + base)     = __halves2half2(__float2half_rn(o0), __float2half_rn(o1));
    *(__half2*)(oh + base + 2) = __halves2half2(__float2half_rn(o2), __float2half_rn(o3));
}

// ---------------- tensor-core GEMM, fp16 1-pass, 4-stage single-sync ------
// block 128x128, 8 warps, warp tile 32x64, BK=32.
// Group accounting: stage kc == commit group kc. wait_group<=2 at top of iter
// kc retires stage kc (3 outstanding: kc,kc+1,kc+2). Load for stage kc+3 is
// issued AFTER compute; it overwrites buf (kc+3)%4 == (kc-1)%4, last read in
// iter kc-1, protected by the single top-of-loop __syncthreads.
#define LDB 80
#define ARR 10240
#define STG_SZ 20480
#define GSTAGES 4
template<int EPI>
__global__ void __launch_bounds__(256, 2)
gemm_mma(const __half* __restrict__ A, const __half* __restrict__ W,
         const float* __restrict__ bias, const float* __restrict__ res,
         float* __restrict__ C, __half* __restrict__ Ch,
         int M, int N, int K)
{
    extern __shared__ char smem[];
    const uint32_t sb = smem_u32(smem);
    const int tid = threadIdx.x;
    const int wid = tid >> 5, lane = tid & 31;
    const int wm = wid & 3, wn = wid >> 2;
    const int m0 = blockIdx.y * 128, n0 = blockIdx.x * 128;

    float acc[2][8][4] = {};
    const int NK = K >> 5;

    auto load_stage = [&](int kc, int buf) {
        int k0 = kc << 5;
        uint32_t stb = sb + buf * STG_SZ;
        #pragma unroll
        for (int i = 0; i < 4; i++) {
            int c = tid + i * 256;
            int arr = c >> 9;
            int cc = c & 511;
            int row = cc >> 2, col = cc & 3;
            const __half* gsrc = (arr ? W + (size_t)(n0 + row) * K
                                      : A + (size_t)(m0 + row) * K) + k0 + col * 8;
            cp_async16(stb + arr * ARR + row * LDB + col * 16, gsrc);
        }
    };

    // prologue: stages 0,1,2 (groups 0,1,2)
    load_stage(0, 0);
    asm volatile("cp.async.commit_group;" ::: "memory");
    load_stage(1, 1);
    asm volatile("cp.async.commit_group;" ::: "memory");
    load_stage(2, 2);
    asm volatile("cp.async.commit_group;" ::: "memory");

    for (int kc = 0; kc < NK; kc++) {
        asm volatile("cp.async.wait_group 2;" ::: "memory");
        __syncthreads();

        uint32_t stb = sb + (kc & 3) * STG_SZ;
        #pragma unroll
        for (int ks = 0; ks < 2; ks++) {
            uint32_t Af[2][4], Bf[8][2];
            int ar = lane & 15, ac = ks * 16 + (lane >> 4) * 8;
            #pragma unroll
            for (int mt = 0; mt < 2; mt++)
                ldsm_x4(Af[mt], stb + (wm * 32 + mt * 16 + ar) * LDB + ac * 2);
            int gq = lane >> 3, l8 = lane & 7;
            int br = (gq >> 1) * 8 + l8, bc = ks * 16 + (gq & 1) * 8;
            #pragma unroll
            for (int p = 0; p < 4; p++) {
                uint32_t a = stb + ARR + (wn * 64 + p * 16 + br) * LDB + bc * 2;
                uint32_t t[4];
                ldsm_x4(t, a);
                Bf[2*p][0] = t[0]; Bf[2*p][1] = t[1];
                Bf[2*p+1][0] = t[2]; Bf[2*p+1][1] = t[3];
            }
            #pragma unroll
            for (int mt = 0; mt < 2; mt++)
                #pragma unroll
                for (int nt = 0; nt < 8; nt++)
                    mma16816(acc[mt][nt], Af[mt], Bf[nt]);
        }

        // issue next stage (group kc+3); empty commit keeps group numbering
        if (kc + 3 < NK) load_stage(kc + 3, (kc + 3) & 3);
        asm volatile("cp.async.commit_group;" ::: "memory");
    }

    // ---- epilogue ----
    int rb = m0 + wm * 32 + (lane >> 2);
    int cb = n0 + wn * 64 + (lane & 3) * 2;
    #pragma unroll
    for (int mt = 0; mt < 2; mt++) {
        #pragma unroll
        for (int half = 0; half < 2; half++) {
            int r = rb + mt * 16 + half * 8;
            #pragma unroll
            for (int nt = 0; nt < 8; nt++) {
                int n = cb + nt * 8;
                float2 bv = *(const float2*)(bias + n);
                float v0 = acc[mt][nt][half * 2 + 0] + bv.x;
                float v1 = acc[mt][nt][half * 2 + 1] + bv.y;
                if (EPI == 2) {
                    float2 rv = *(const float2*)(res + (size_t)r * N + n);
                    v0 += rv.x; v1 += rv.y;
                    *(float2*)(C + (size_t)r * N + n) = make_float2(v0, v1);
                } else if (EPI == 3) {
                    v0 = 0.5f * v0 * (1.0f + erff(v0 * 0.70710678118654752f));
                    v1 = 0.5f * v1 * (1.0f + erff(v1 * 0.70710678118654752f));
                    *(__half2*)(Ch + (size_t)r * N + n) =
                        __halves2half2(__float2half_rn(v0), __float2half_rn(v1));
                } else if (EPI == 4) {
                    int which = n >> 10, n2 = n & 1023;
                    float scl = (which == 0) ? (1.0f / 32.0f) : 1.0f;
                    v0 *= scl; v1 *= scl;
                    int b_ = r >> 10, s = r & 1023, hh = n2 >> 6, dh = n2 & 63;
                    size_t off = (size_t)which * (ROWS * DD)
                               + ((size_t)(b_ * HH + hh) * SS + s) * DHH + dh;
                    *(__half2*)(Ch + off) =
                        __halves2half2(__float2half_rn(v0), __float2half_rn(v1));
                }
            }
        }
    }
}

// ---------------- Flash attention, fp16, 4-stage single-sync KV -----------
// Groups: 0=Q, 1..3=stages 0..2, then iter t issues group 4+t = stage t+3.
// At top of iter t: outstanding = stages t,t+1,t+2 (+Q at t=0) -> wait<=2
// retires Q and stage t at t=0, stage t afterwards.
#define LDK 144
#define FQ_SZ 18432
#define FST0  18432
#define FARR  9216
#define FST_SZ 18432
#define FSTAGES 4
#define FLASH_SMEM (FST0 + FSTAGES*FST_SZ)   // 92160
__global__ void __launch_bounds__(256, 2)
flash_mma(const __half* __restrict__ Q_, const __half* __restrict__ K_,
          const __half* __restrict__ V_, __half* __restrict__ O_)
{
    extern __shared__ char smc[];
    const uint32_t sb = smem_u32(smc);
    int tid = threadIdx.x, lane = tid & 31, w = tid >> 5;
    int bh = blockIdx.y, q0 = blockIdx.x * 128;
    size_t qbase = ((size_t)bh * SS + q0) * DHH;
    size_t kvbase = (size_t)bh * SS * DHH;
    const int NT = SS / 64;

    // group 0: Q
    #pragma unroll
    for (int i = 0; i < 4; i++) {
        int c = tid + i * 256;
        int row = c >> 3, col = c & 7;
        cp_async16(sb + row * LDK + col * 16, Q_ + qbase + row * 64 + col * 8);
    }
    asm volatile("cp.async.commit_group;" ::: "memory");
    auto load_stage = [&](int t, int buf) {
        size_t base = kvbase + (size_t)t * 64 * DHH;
        #pragma unroll
        for (int i = 0; i < 4; i++) {
            int c = tid + i * 256;
            int arr = c >> 9, cc = c & 511;
            int row = cc >> 3, col = cc & 7;
            const __half* src = (arr ? V_ : K_) + base + row * 64 + col * 8;
            cp_async16(sb + FST0 + buf * FST_SZ + arr * FARR + row * LDK + col * 16, src);
        }
    };
    // groups 1..3: stages 0..2
    load_stage(0, 0);
    asm volatile("cp.async.commit_group;" ::: "memory");
    load_stage(1, 1);
    asm volatile("cp.async.commit_group;" ::: "memory");
    load_stage(2, 2);
    asm volatile("cp.async.commit_group;" ::: "memory");

    uint32_t qf[4][4];
    float m2[2] = {-1e30f, -1e30f}, l2[2] = {0.f, 0.f};
    float acc_o[8][4] = {};

    for (int t = 0; t < NT; t++) {
        asm volatile("cp.async.wait_group 2;" ::: "memory");
        __syncthreads();
        if (t == 0) {
            #pragma unroll
            for (int ks = 0; ks < 4; ks++)
                ldsm_x4(qf[ks], sb + (w * 16 + (lane & 15)) * LDK + ks * 32 + (lane >> 4) * 16);
        }
        uint32_t stb = sb + FST0 + (t & 3) * FST_SZ;

        float s[8][4] = {};
        int gq = lane >> 3, l8 = lane & 7;
        int br = (gq >> 1) * 8 + l8;
        #pragma unroll
        for (int ks = 0; ks < 4; ks++) {
            uint32_t Bf[8][2];
            int bcB = ks * 32 + (gq & 1) * 16;
            #pragma unroll
            for (int p = 0; p < 4; p++) {
                uint32_t a = stb + (p * 16 + br) * LDK + bcB;
                uint32_t t4[4];
                ldsm_x4(t4, a);
                Bf[2*p][0] = t4[0]; Bf[2*p][1] = t4[1];
                Bf[2*p+1][0] = t4[2]; Bf[2*p+1][1] = t4[3];
            }
            #pragma unroll
            for (int nt = 0; nt < 8; nt++)
                mma16816(s[nt], qf[ks], Bf[nt]);
        }

        float rm0 = -1e30f, rm1 = -1e30f;
        #pragma unroll
        for (int nt = 0; nt < 8; nt++) {
            rm0 = fmaxf(rm0, fmaxf(s[nt][0], s[nt][1]));
            rm1 = fmaxf(rm1, fmaxf(s[nt][2], s[nt][3]));
        }
        rm0 = fmaxf(rm0, __shfl_xor_sync(0xffffffffu, rm0, 1));
        rm0 = fmaxf(rm0, __shfl_xor_sync(0xffffffffu, rm0, 2));
        rm1 = fmaxf(rm1, __shfl_xor_sync(0xffffffffu, rm1, 1));
        rm1 = fmaxf(rm1, __shfl_xor_sync(0xffffffffu, rm1, 2));
        float mn0 = fmaxf(m2[0], rm0), mn1 = fmaxf(m2[1], rm1);
        float al0 = __expf(m2[0] - mn0), al1 = __expf(m2[1] - mn1);
        float rs0 = 0.f, rs1 = 0.f;
        #pragma unroll
        for (int nt = 0; nt < 8; nt++) {
            s[nt][0] = __expf(s[nt][0] - mn0);
            s[nt][1] = __expf(s[nt][1] - mn0);
            s[nt][2] = __expf(s[nt][2] - mn1);
            s[nt][3] = __expf(s[nt][3] - mn1);
            rs0 += s[nt][0] + s[nt][1];
            rs1 += s[nt][2] + s[nt][3];
        }
        rs0 += __shfl_xor_sync(0xffffffffu, rs0, 1);
        rs0 += __shfl_xor_sync(0xffffffffu, rs0, 2);
        rs1 += __shfl_xor_sync(0xffffffffu, rs1, 1);
        rs1 += __shfl_xor_sync(0xffffffffu, rs1, 2);
        l2[0] = l2[0] * al0 + rs0;
        l2[1] = l2[1] * al1 + rs1;
        m2[0] = mn0; m2[1] = mn1;
        #pragma unroll
        for (int nt = 0; nt < 8; nt++) {
            acc_o[nt][0] *= al0; acc_o[nt][1] *= al0;
            acc_o[nt][2] *= al1; acc_o[nt][3] *= al1;
        }

        int vr = ((lane >> 3) & 1) * 8 + (lane & 7);
        int vcb = ((lane >> 4) * 8) * 2;
        #pragma unroll
        for (int ks = 0; ks < 4; ks++) {
            uint32_t pf[4];
            #pragma unroll
            for (int q2 = 0; q2 < 2; q2++) {
                pf[2*q2]     = pack_h2(__float2half_rn(s[2*ks + q2][0]), __float2half_rn(s[2*ks + q2][1]));
                pf[2*q2 + 1] = pack_h2(__float2half_rn(s[2*ks + q2][2]), __float2half_rn(s[2*ks + q2][3]));
            }
            uint32_t Vf[8][2];
            #pragma unroll
            for (int np = 0; np < 4; np++) {
                uint32_t a = stb + FARR + (ks * 16 + vr) * LDK + np * 32 + vcb;
                uint32_t t4[4];
                ldsm_x4_t(t4, a);
                Vf[2*np][0] = t4[0]; Vf[2*np][1] = t4[1];
                Vf[2*np+1][0] = t4[2]; Vf[2*np+1][1] = t4[3];
            }
            #pragma unroll
            for (int nt = 0; nt < 8; nt++)
                mma16816(acc_o[nt], pf, Vf[nt]);
        }

        // issue next stage (group 4+t = stage t+3); empty commit otherwise
        if (t + 3 < NT) load_stage(t + 3, (t + 3) & 3);
        asm volatile("cp.async.commit_group;" ::: "memory");
    }

    float inv0 = 1.0f / l2[0], inv1 = 1.0f / l2[1];
    int g = lane >> 2;
    int bb = bh >> 4, hh = bh & 15;
    int r_lo = q0 + w * 16 + g, r_hi = r_lo + 8;
    int cbase = hh * 64 + (lane & 3) * 2;
    #pragma unroll
    for (int nt = 0; nt < 8; nt++) {
        int cc = cbase + nt * 8;
        size_t off_lo = ((size_t)bb * SS + r_lo) * DD + cc;
        size_t off_hi = ((size_t)bb * SS + r_hi) * DD + cc;
        *(__half2*)(O_ + off_lo) = __halves2half2(
            __float2half_rn(acc_o[nt][0] * inv0), __float2half_rn(acc_o[nt][1] * inv0));
        *(__half2*)(O_ + off_hi) = __halves2half2(
            __float2half_rn(acc_o[nt][2] * inv1), __float2half_rn(acc_o[nt][3] * inv1));
    }
}

// ---------------- launch ----------------
extern "C" void kernel_launch(void* const* d_in, const int* in_sizes, int n_in,
                              void* d_out, int out_size)
{
    const float* x    = (const float*)d_in[0];
    const float* wq   = (const float*)d_in[1];
    const float* bq   = (const float*)d_in[2];
    const float* wk   = (const float*)d_in[3];
    const float* bk   = (const float*)d_in[4];
    const float* wv   = (const float*)d_in[5];
    const float* bv   = (const float*)d_in[6];
    const float* wo   = (const float*)d_in[7];
    const float* bo   = (const float*)d_in[8];
    const float* g1   = (const float*)d_in[9];
    const float* b1   = (const float*)d_in[10];
    const float* g2   = (const float*)d_in[11];
    const float* b2   = (const float*)d_in[12];
    const float* wfc1 = (const float*)d_in[13];
    const float* bfc1 = (const float*)d_in[14];
    const float* wfc2 = (const float*)d_in[15];
    const float* bfc2 = (const float*)d_in[16];
    float* out = (float*)d_out;

    float *o1, *bqkv;
    cudaGetSymbolAddress((void**)&o1,   g_o1);
    cudaGetSymbolAddress((void**)&bqkv, g_bqkv);
    __half *xa, *mid, *qkv;
    cudaGetSymbolAddress((void**)&xa,  g_x);
    cudaGetSymbolAddress((void**)&mid, g_mid);
    cudaGetSymbolAddress((void**)&qkv, g_qkv);
    __half *wqkvt, *wot, *w1t, *w2t;
    cudaGetSymbolAddress((void**)&wqkvt, g_wqkvt);
    cudaGetSymbolAddress((void**)&wot,   g_wot);
    cudaGetSymbolAddress((void**)&w1t,   g_w1t);
    cudaGetSymbolAddress((void**)&w2t,   g_w2t);

    const int GEMM_SMEM = GSTAGES * STG_SZ;  // 81920
    cudaFuncSetAttribute(gemm_mma<2>, cudaFuncAttributeMaxDynamicSharedMemorySize, GEMM_SMEM);
    cudaFuncSetAttribute(gemm_mma<3>, cudaFuncAttributeMaxDynamicSharedMemorySize, GEMM_SMEM);
    cudaFuncSetAttribute(gemm_mma<4>, cudaFuncAttributeMaxDynamicSharedMemorySize, GEMM_SMEM);
    cudaFuncSetAttribute(flash_mma, cudaFuncAttributeMaxDynamicSharedMemorySize, FLASH_SMEM);

    // 0. weights + bias pack + LN1, one launch
    wconv_all<<<16385, dim3(32, 8)>>>(wq, wk, wv, wo, wfc1, wfc2, bq, bk, bv,
                                      x, g1, b1, xa);

    // 1. fused QKV projection -> (3,B,H,S,DH) fp16
    gemm_mma<4><<<dim3(3 * DD / 128, ROWS / 128), 256, GEMM_SMEM>>>(
        xa, wqkvt, bqkv, nullptr, nullptr, qkv, ROWS, 3 * DD, DD);

    // 2. attention -> fp16 (B,S,D) into xa
    flash_mma<<<dim3(SS / 128, BB * HH), 256, FLASH_SMEM>>>(
        qkv, qkv + ROWS * DD, qkv + 2 * ROWS * DD, xa);

    // 3. output projection + residual(x) -> o1 fp32
    gemm_mma<2><<<dim3(DD / 128, ROWS / 128), 256, GEMM_SMEM>>>(
        xa, wot, bo, x, o1, nullptr, ROWS, DD, DD);

    // 4. LN2 -> fp16
    layernorm_f16<<<ROWS, 256>>>(o1, g2, b2, xa);

    // 5. FC1 + GELU -> fp16 mid
    gemm_mma<3><<<dim3(FFN / 128, ROWS / 128), 256, GEMM_SMEM>>>(
        xa, w1t, bfc1, nullptr, nullptr, mid, ROWS, FFN, DD);

    // 6. FC2 + residual(o1) -> out
    gemm_mma<2><<<dim3(DD / 128, ROWS / 128), 256, GEMM_SMEM>>>(
        mid, w2t, bfc2, o1, out, nullptr, ROWS, DD, FFN);
}